// round 3
// baseline (speedup 1.0000x reference)
#include <cuda_runtime.h>
#include <cuda_bf16.h>

// ---------------- problem constants ----------------
#define BSZ 2
#define TLEN 1024
#define HID 2048
#define NHEADS 2
#define HH 6
#define DK 256
#define DV 512
#define KEY_DIM 1536   // HH*DK
#define VAL_DIM 3072   // HH*DV
#define RROWS 2048     // BSZ*TLEN

// ---------------- scratch (static device memory; no allocs) ----------------
__device__ float g_qx [RROWS*KEY_DIM];
__device__ float g_kx0[RROWS*KEY_DIM];
__device__ float g_kx1[RROWS*KEY_DIM];
__device__ float g_vx0[RROWS*VAL_DIM];
__device__ float g_vx1[RROWS*VAL_DIM];
__device__ float g_gate[RROWS*VAL_DIM];
__device__ float g_qn [RROWS*KEY_DIM];
__device__ float g_kn0[RROWS*KEY_DIM];
__device__ float g_kn1[RROWS*KEY_DIM];
__device__ float g_vs0[RROWS*VAL_DIM];
__device__ float g_vs1[RROWS*VAL_DIM];
__device__ float g_ob [RROWS*VAL_DIM];
__device__ float g_yb [RROWS*VAL_DIM];
__device__ float g_bx0[RROWS*HH];
__device__ float g_bx1[RROWS*HH];
__device__ float g_ax [RROWS*HH];
__device__ float g_be0[RROWS*HH];
__device__ float g_be1[RROWS*HH];
__device__ float g_gd [RROWS*HH];

// ---------------- generic fp32 tiled GEMM: C[M,N] = A[M,K] @ B[K,N] ----------------
// M,N multiples of 64; K multiple of 16. 256 threads, 64x64 tile, 4x4 microtile.
__global__ __launch_bounds__(256) void gemm64(
    const float* __restrict__ A, const float* __restrict__ Bm,
    float* __restrict__ C, int M, int N, int K)
{
    __shared__ __align__(16) float As[16][68];
    __shared__ __align__(16) float Bs[16][68];
    const int tid = threadIdx.x;
    const int bm = blockIdx.y * 64, bn = blockIdx.x * 64;
    const int tx = tid & 15, ty = tid >> 4;
    const int mload = tid >> 2, kA = (tid & 3) << 2;
    const int kB = tid >> 4,  nload = (tid & 15) << 2;

    float acc[4][4];
#pragma unroll
    for (int i = 0; i < 4; i++)
#pragma unroll
        for (int j = 0; j < 4; j++) acc[i][j] = 0.f;

    for (int kt = 0; kt < K; kt += 16) {
        float4 a4 = *reinterpret_cast<const float4*>(&A[(size_t)(bm + mload) * K + kt + kA]);
        float4 b4 = *reinterpret_cast<const float4*>(&Bm[(size_t)(kt + kB) * N + bn + nload]);
        __syncthreads();
        As[kA + 0][mload] = a4.x; As[kA + 1][mload] = a4.y;
        As[kA + 2][mload] = a4.z; As[kA + 3][mload] = a4.w;
        *reinterpret_cast<float4*>(&Bs[kB][nload]) = b4;
        __syncthreads();
#pragma unroll
        for (int k = 0; k < 16; k++) {
            float a[4], b[4];
#pragma unroll
            for (int i = 0; i < 4; i++) a[i] = As[k][ty * 4 + i];
#pragma unroll
            for (int j = 0; j < 4; j++) b[j] = Bs[k][tx * 4 + j];
#pragma unroll
            for (int i = 0; i < 4; i++)
#pragma unroll
                for (int j = 0; j < 4; j++) acc[i][j] = fmaf(a[i], b[j], acc[i][j]);
        }
    }
#pragma unroll
    for (int i = 0; i < 4; i++) {
        int row = bm + ty * 4 + i;
#pragma unroll
        for (int j = 0; j < 4; j++)
            C[(size_t)row * N + bn + tx * 4 + j] = acc[i][j];
    }
}

// ---------------- tiny-N GEMM (N=6): one block per row ----------------
__global__ __launch_bounds__(128) void gemm6(
    const float* __restrict__ A, const float* __restrict__ W,
    float* __restrict__ C, int K)
{
    __shared__ float red[128 * 8];
    const int r = blockIdx.x, tid = threadIdx.x;
    float acc[6] = {0.f, 0.f, 0.f, 0.f, 0.f, 0.f};
    const float* arow = A + (size_t)r * K;
    for (int k = tid; k < K; k += 128) {
        float a = arow[k];
#pragma unroll
        for (int j = 0; j < 6; j++) acc[j] = fmaf(a, W[k * 6 + j], acc[j]);
    }
#pragma unroll
    for (int j = 0; j < 6; j++) red[tid * 8 + j] = acc[j];
    __syncthreads();
    for (int s = 64; s > 0; s >>= 1) {
        if (tid < s) {
#pragma unroll
            for (int j = 0; j < 6; j++) red[tid * 8 + j] += red[(tid + s) * 8 + j];
        }
        __syncthreads();
    }
    if (tid < 6) C[r * 6 + tid] = red[tid];
}

// ---------------- activations for beta / g ----------------
__global__ void act_bg(
    const float* __restrict__ bx0, const float* __restrict__ bx1,
    const float* __restrict__ ax,  const float* __restrict__ A_log,
    const float* __restrict__ dtb, float* __restrict__ be0,
    float* __restrict__ be1, float* __restrict__ gd)
{
    int i = blockIdx.x * blockDim.x + threadIdx.x;
    if (i >= RROWS * HH) return;
    int hh = i % HH;
    be0[i] = 1.f / (1.f + expf(-bx0[i]));
    be1[i] = 1.f / (1.f + expf(-bx1[i]));
    float z = ax[i] + dtb[hh];
    float sp = (z > 20.f) ? z : log1pf(expf(z));
    gd[i] = -expf(A_log[hh]) * sp;
}

// ---------------- causal depthwise conv(4) + SiLU + per-head L2 norm (q/k path) ----------------
// grid (RROWS, HH), 256 threads (== DK)
__global__ __launch_bounds__(256) void conv_silu_norm(
    const float* __restrict__ Z, const float* __restrict__ W,
    float* __restrict__ Out, float outscale)
{
    const int r = blockIdx.x, h = blockIdx.y, tid = threadIdx.x;
    const int b = r >> 10, t = r & 1023;
    const int c = h * DK + tid;
    float acc = 0.f;
#pragma unroll
    for (int j = 0; j < 4; j++) {
        int tj = t - 3 + j;
        if (tj >= 0) acc = fmaf(Z[(size_t)(b * TLEN + tj) * KEY_DIM + c], W[c * 4 + j], acc);
    }
    float y = acc / (1.f + expf(-acc));   // silu
    __shared__ float sred[256];
    sred[tid] = y * y;
    __syncthreads();
    for (int s = 128; s > 0; s >>= 1) {
        if (tid < s) sred[tid] += sred[tid + s];
        __syncthreads();
    }
    float scale = rsqrtf(sred[0] + 1e-12f) * outscale;
    Out[(size_t)r * KEY_DIM + c] = y * scale;
}

// ---------------- conv(4) + SiLU for v path (elementwise over R*VAL_DIM) ----------------
__global__ void conv_silu_v(
    const float* __restrict__ Z, const float* __restrict__ W,
    float* __restrict__ Out)
{
    int idx = blockIdx.x * blockDim.x + threadIdx.x;
    if (idx >= RROWS * VAL_DIM) return;
    int c = idx % VAL_DIM;
    int r = idx / VAL_DIM;
    int b = r >> 10, t = r & 1023;
    float acc = 0.f;
#pragma unroll
    for (int j = 0; j < 4; j++) {
        int tj = t - 3 + j;
        if (tj >= 0) acc = fmaf(Z[(size_t)(b * TLEN + tj) * VAL_DIM + c], W[c * 4 + j], acc);
    }
    Out[idx] = acc / (1.f + expf(-acc));
}

// ---------------- packed f32x2 helpers ----------------
union F2U { float2 f; unsigned long long u; };

__device__ __forceinline__ F2U ffma2(F2U a, F2U b, F2U c) {
    F2U r;
    asm("fma.rn.f32x2 %0, %1, %2, %3;" : "=l"(r.u) : "l"(a.u), "l"(b.u), "l"(c.u));
    return r;
}
__device__ __forceinline__ F2U fmul2(F2U a, F2U b) {
    F2U r;
    asm("mul.rn.f32x2 %0, %1, %2;" : "=l"(r.u) : "l"(a.u), "l"(b.u));
    return r;
}
__device__ __forceinline__ float hsum16(float v) {
    v += __shfl_xor_sync(0xffffffffu, v, 8);
    v += __shfl_xor_sync(0xffffffffu, v, 4);
    v += __shfl_xor_sync(0xffffffffu, v, 2);
    v += __shfl_xor_sync(0xffffffffu, v, 1);
    return v;
}

// ---------------- gated delta-rule recurrence ----------------
// Columns of S are independent: half-warp (16 lanes) owns one DV-column,
// state S[:,col] (DK=256 floats) lives in registers as 8 packed float2.
// One macro step fuses the even (k0/v0/beta0, decayed) and odd (k1/v1/beta1 + q-readout)
// interleaved sub-steps.
// grid (BSZ*HH = 12, DV/16 = 32); 256 threads = 8 warps = 16 columns per block.
__global__ __launch_bounds__(256, 3) void delta_recur(
    const float* __restrict__ Qn,  const float* __restrict__ Kn0, const float* __restrict__ Kn1,
    const float* __restrict__ Vs0, const float* __restrict__ Vs1,
    const float* __restrict__ Be0, const float* __restrict__ Be1,
    const float* __restrict__ Gd,  float* __restrict__ O)
{
    const int bh = blockIdx.x;
    const int b = bh / HH, h = bh % HH;
    const int tid = threadIdx.x;
    const int warp = tid >> 5, lane = tid & 31;
    const int half = lane >> 4, l0 = lane & 15;
    const int col = blockIdx.y * 16 + warp * 2 + half;

    __shared__ __align__(16) float sk0[256], sk1[256], sq[256];
    __shared__ float ssc[4];

    F2U S[8];
#pragma unroll
    for (int j = 0; j < 8; j++) S[j].u = 0ull;

    const float2* pk0 = reinterpret_cast<const float2*>(sk0);
    const float2* pk1 = reinterpret_cast<const float2*>(sk1);
    const float2* pq  = reinterpret_cast<const float2*>(sq);

    for (int t = 0; t < TLEN; t++) {
        const int r = b * TLEN + t;
        const size_t kbase = (size_t)r * KEY_DIM + h * DK;
        __syncthreads();
        sk0[tid] = Kn0[kbase + tid];
        sk1[tid] = Kn1[kbase + tid];
        sq [tid] = Qn [kbase + tid];
        if (tid == 0) {
            int gi = r * HH + h;
            ssc[0] = Gd[gi]; ssc[1] = Be0[gi]; ssc[2] = Be1[gi];
        }
        __syncthreads();
        const float decay = expf(ssc[0]);
        const float bb0 = ssc[1], bb1 = ssc[2];
        const size_t vbase = (size_t)r * VAL_DIM + h * DV + col;
        const float v0 = Vs0[vbase];
        const float v1 = Vs1[vbase];

        F2U rk[8], acc;
        // ---- sub-step 0: decay + (k0, v0, beta0) ----
#pragma unroll
        for (int j = 0; j < 8; j++) rk[j].f = pk0[j * 16 + l0];
        acc.u = 0ull;
#pragma unroll
        for (int j = 0; j < 8; j++) acc = ffma2(rk[j], S[j], acc);
        float dot0 = hsum16(acc.f.x + acc.f.y) * decay;   // k0 . (decay*S)
        float u0 = (v0 - dot0) * bb0;
        F2U dec2; dec2.f = make_float2(decay, decay);
        F2U u0v;  u0v.f  = make_float2(u0, u0);
#pragma unroll
        for (int j = 0; j < 8; j++) S[j] = ffma2(S[j], dec2, fmul2(rk[j], u0v));
        // ---- sub-step 1: (k1, v1, beta1), no decay ----
#pragma unroll
        for (int j = 0; j < 8; j++) rk[j].f = pk1[j * 16 + l0];
        acc.u = 0ull;
#pragma unroll
        for (int j = 0; j < 8; j++) acc = ffma2(rk[j], S[j], acc);
        float dot1 = hsum16(acc.f.x + acc.f.y);
        float u1 = (v1 - dot1) * bb1;
        F2U u1v; u1v.f = make_float2(u1, u1);
#pragma unroll
        for (int j = 0; j < 8; j++) S[j] = ffma2(rk[j], u1v, S[j]);
        // ---- readout: o = q . S ----
#pragma unroll
        for (int j = 0; j < 8; j++) rk[j].f = pq[j * 16 + l0];
        acc.u = 0ull;
#pragma unroll
        for (int j = 0; j < 8; j++) acc = ffma2(rk[j], S[j], acc);
        float outv = hsum16(acc.f.x + acc.f.y);
        if (l0 == 0) O[(size_t)(r * HH + h) * DV + col] = outv;
    }
}

// ---------------- RMS norm over DV + gated SiLU ----------------
// grid (RROWS, HH), 256 threads, 2 elements each
__global__ __launch_bounds__(256) void rms_gate(
    const float* __restrict__ Ob, const float* __restrict__ Gx,
    const float* __restrict__ onw, float* __restrict__ Y)
{
    const int r = blockIdx.x, h = blockIdx.y, tid = threadIdx.x;
    const size_t base = (size_t)(r * HH + h) * DV;
    float o0 = Ob[base + tid], o1 = Ob[base + tid + 256];
    __shared__ float sred[256];
    sred[tid] = o0 * o0 + o1 * o1;
    __syncthreads();
    for (int s = 128; s > 0; s >>= 1) {
        if (tid < s) sred[tid] += sred[tid + s];
        __syncthreads();
    }
    float scale = rsqrtf(sred[0] * (1.f / 512.f) + 1e-5f);
    float g0 = Gx[base + tid], g1 = Gx[base + tid + 256];
    Y[base + tid]       = o0 * scale * onw[tid]       * (g0 / (1.f + expf(-g0)));
    Y[base + tid + 256] = o1 * scale * onw[tid + 256] * (g1 / (1.f + expf(-g1)));
}

// ---------------- launch ----------------
extern "C" void kernel_launch(void* const* d_in, const int* in_sizes, int n_in,
                              void* d_out, int out_size)
{
    const float* x     = (const float*)d_in[0];
    const float* q_w   = (const float*)d_in[1];
    const float* k_ws  = (const float*)d_in[2];
    const float* v_ws  = (const float*)d_in[3];
    const float* b_ws  = (const float*)d_in[4];
    const float* a_w   = (const float*)d_in[5];
    const float* g_w   = (const float*)d_in[6];
    const float* o_w   = (const float*)d_in[7];
    const float* qcw   = (const float*)d_in[8];
    const float* kcw   = (const float*)d_in[9];
    const float* vcw   = (const float*)d_in[10];
    const float* A_log = (const float*)d_in[11];
    const float* dtb   = (const float*)d_in[12];
    const float* onw   = (const float*)d_in[13];
    float* out = (float*)d_out;

    float *qx, *kx0, *kx1, *vx0, *vx1, *gate, *qn, *kn0, *kn1, *vs0, *vs1, *ob, *yb;
    float *bx0, *bx1, *ax, *be0, *be1, *gd;
    cudaGetSymbolAddress((void**)&qx,  g_qx);
    cudaGetSymbolAddress((void**)&kx0, g_kx0);
    cudaGetSymbolAddress((void**)&kx1, g_kx1);
    cudaGetSymbolAddress((void**)&vx0, g_vx0);
    cudaGetSymbolAddress((void**)&vx1, g_vx1);
    cudaGetSymbolAddress((void**)&gate, g_gate);
    cudaGetSymbolAddress((void**)&qn,  g_qn);
    cudaGetSymbolAddress((void**)&kn0, g_kn0);
    cudaGetSymbolAddress((void**)&kn1, g_kn1);
    cudaGetSymbolAddress((void**)&vs0, g_vs0);
    cudaGetSymbolAddress((void**)&vs1, g_vs1);
    cudaGetSymbolAddress((void**)&ob,  g_ob);
    cudaGetSymbolAddress((void**)&yb,  g_yb);
    cudaGetSymbolAddress((void**)&bx0, g_bx0);
    cudaGetSymbolAddress((void**)&bx1, g_bx1);
    cudaGetSymbolAddress((void**)&ax,  g_ax);
    cudaGetSymbolAddress((void**)&be0, g_be0);
    cudaGetSymbolAddress((void**)&be1, g_be1);
    cudaGetSymbolAddress((void**)&gd,  g_gd);

    // 1) projections
    gemm64<<<dim3(KEY_DIM / 64, RROWS / 64), 256>>>(x, q_w, qx, RROWS, KEY_DIM, HID);
    gemm64<<<dim3(KEY_DIM / 64, RROWS / 64), 256>>>(x, k_ws, kx0, RROWS, KEY_DIM, HID);
    gemm64<<<dim3(KEY_DIM / 64, RROWS / 64), 256>>>(x, k_ws + (size_t)HID * KEY_DIM, kx1, RROWS, KEY_DIM, HID);
    gemm64<<<dim3(VAL_DIM / 64, RROWS / 64), 256>>>(x, v_ws, vx0, RROWS, VAL_DIM, HID);
    gemm64<<<dim3(VAL_DIM / 64, RROWS / 64), 256>>>(x, v_ws + (size_t)HID * VAL_DIM, vx1, RROWS, VAL_DIM, HID);
    gemm64<<<dim3(VAL_DIM / 64, RROWS / 64), 256>>>(x, g_w, gate, RROWS, VAL_DIM, HID);
    gemm6<<<RROWS, 128>>>(x, b_ws, bx0, HID);
    gemm6<<<RROWS, 128>>>(x, b_ws + (size_t)HID * HH, bx1, HID);
    gemm6<<<RROWS, 128>>>(x, a_w, ax, HID);

    // 2) activations / conv / norms
    act_bg<<<(RROWS * HH + 255) / 256, 256>>>(bx0, bx1, ax, A_log, dtb, be0, be1, gd);
    conv_silu_norm<<<dim3(RROWS, HH), 256>>>(qx,  qcw, qn, 0.0625f);  // * DK^-0.5
    conv_silu_norm<<<dim3(RROWS, HH), 256>>>(kx0, kcw, kn0, 1.f);
    conv_silu_norm<<<dim3(RROWS, HH), 256>>>(kx1, kcw + KEY_DIM * 4, kn1, 1.f);
    conv_silu_v<<<(RROWS * VAL_DIM + 255) / 256, 256>>>(vx0, vcw, vs0);
    conv_silu_v<<<(RROWS * VAL_DIM + 255) / 256, 256>>>(vx1, vcw + VAL_DIM * 4, vs1);

    // 3) sequential gated delta rule
    delta_recur<<<dim3(BSZ * HH, DV / 16), 256>>>(qn, kn0, kn1, vs0, vs1, be0, be1, gd, ob);

    // 4) output norm + gate + final projection
    rms_gate<<<dim3(RROWS, HH), 256>>>(ob, gate, onw, yb);
    gemm64<<<dim3(HID / 64, RROWS / 64), 256>>>(yb, o_w, out, RROWS, HID, VAL_DIM);
}

// round 6
// speedup vs baseline: 1.7251x; 1.7251x over previous
#include <cuda_runtime.h>
#include <cuda_bf16.h>
#include <cstdint>

// ---------------- problem constants ----------------
#define BSZ 2
#define TLEN 1024
#define HID 2048
#define NHEADS 2
#define HH 6
#define DK 256
#define DV 512
#define KEY_DIM 1536   // HH*DK
#define VAL_DIM 3072   // HH*DV
#define RROWS 2048     // BSZ*TLEN

// ---------------- scratch (static device memory; no allocs) ----------------
__device__ float g_qx [RROWS*KEY_DIM];
__device__ float g_kx0[RROWS*KEY_DIM];
__device__ float g_kx1[RROWS*KEY_DIM];
__device__ float g_vx0[RROWS*VAL_DIM];
__device__ float g_vx1[RROWS*VAL_DIM];
__device__ float g_gate[RROWS*VAL_DIM];
__device__ float g_qn [RROWS*KEY_DIM];
__device__ float g_kn0[RROWS*KEY_DIM];
__device__ float g_kn1[RROWS*KEY_DIM];
__device__ float g_vs0[RROWS*VAL_DIM];
__device__ float g_vs1[RROWS*VAL_DIM];
__device__ float g_ob [RROWS*VAL_DIM];
__device__ float g_yb [RROWS*VAL_DIM];
__device__ float g_bx0[RROWS*HH];
__device__ float g_bx1[RROWS*HH];
__device__ float g_ax [RROWS*HH];
__device__ float g_be0[RROWS*HH];
__device__ float g_be1[RROWS*HH];
__device__ float g_gd [RROWS*HH];

// ================= helpers =================
__device__ __forceinline__ uint32_t smem_u32(const void* p) {
    uint32_t a;
    asm("{ .reg .u64 t; cvta.to.shared.u64 t, %1; cvt.u32.u64 %0, t; }" : "=r"(a) : "l"(p));
    return a;
}

__device__ __forceinline__ void ldmx4(uint32_t* r, uint32_t addr) {
    asm volatile("ldmatrix.sync.aligned.m8n8.x4.shared.b16 {%0,%1,%2,%3}, [%4];"
        : "=r"(r[0]), "=r"(r[1]), "=r"(r[2]), "=r"(r[3]) : "r"(addr));
}
__device__ __forceinline__ void ldmx2(uint32_t* r, uint32_t addr) {
    asm volatile("ldmatrix.sync.aligned.m8n8.x2.shared.b16 {%0,%1}, [%2];"
        : "=r"(r[0]), "=r"(r[1]) : "r"(addr));
}
__device__ __forceinline__ void mma16816(float* c, const uint32_t* a, const uint32_t* b) {
    asm volatile(
        "mma.sync.aligned.m16n8k16.row.col.f32.bf16.bf16.f32 "
        "{%0,%1,%2,%3}, {%4,%5,%6,%7}, {%8,%9}, {%0,%1,%2,%3};"
        : "+f"(c[0]), "+f"(c[1]), "+f"(c[2]), "+f"(c[3])
        : "r"(a[0]), "r"(a[1]), "r"(a[2]), "r"(a[3]), "r"(b[0]), "r"(b[1]));
}

// convert 8 fp32 -> 8 bf16 hi (16B) + 8 bf16 lo (16B)
__device__ __forceinline__ void cvt8(const float* e, uint4& hi, uint4& lo) {
    __nv_bfloat162 h[4];
    float l[8];
#pragma unroll
    for (int i = 0; i < 4; i++) {
        h[i] = __floats2bfloat162_rn(e[2*i], e[2*i+1]);
        l[2*i]   = e[2*i]   - __low2float(h[i]);
        l[2*i+1] = e[2*i+1] - __high2float(h[i]);
    }
    __nv_bfloat162 lw[4];
#pragma unroll
    for (int i = 0; i < 4; i++) lw[i] = __floats2bfloat162_rn(l[2*i], l[2*i+1]);
    hi.x = *reinterpret_cast<uint32_t*>(&h[0]); hi.y = *reinterpret_cast<uint32_t*>(&h[1]);
    hi.z = *reinterpret_cast<uint32_t*>(&h[2]); hi.w = *reinterpret_cast<uint32_t*>(&h[3]);
    lo.x = *reinterpret_cast<uint32_t*>(&lw[0]); lo.y = *reinterpret_cast<uint32_t*>(&lw[1]);
    lo.z = *reinterpret_cast<uint32_t*>(&lw[2]); lo.w = *reinterpret_cast<uint32_t*>(&lw[3]);
}

// ================= HMMA (mma.sync) bf16x3 GEMM =================
// C[M,N] = A[M,K] @ B[K,N], fp32 in/out, bf16 hi/lo split, 3 mma passes per k-step.
// Tile 128x128, BK=32, 256 threads (8 warps, each 64x32). Double-buffered SMEM.
// SMEM stage layout (bytes): Ahi[128x40b16]=10240 | Alo=10240 | Bhi[n][k]=10240 | Blo=10240
#define HP 80          // row pitch bytes (40 bf16): (5m+c) mod 8 -> conflict-free ldmatrix
#define HSTAGE 40960
#define HSMEM (2 * HSTAGE)

__device__ __forceinline__ void ldg_tiles(
    const float* __restrict__ A, const float* __restrict__ B,
    int bm, int bn, int kt, int N, int K, int tid, float* ra, float* rb)
{
    const int r = tid >> 2, kq = (tid & 3) * 8;
#pragma unroll
    for (int p = 0; p < 2; p++) {
        const float* src = A + (size_t)(bm + r + p * 64) * K + kt + kq;
        float4 f0 = *reinterpret_cast<const float4*>(src);
        float4 f1 = *reinterpret_cast<const float4*>(src + 4);
        ra[p*8+0]=f0.x; ra[p*8+1]=f0.y; ra[p*8+2]=f0.z; ra[p*8+3]=f0.w;
        ra[p*8+4]=f1.x; ra[p*8+5]=f1.y; ra[p*8+6]=f1.z; ra[p*8+7]=f1.w;
    }
    const int n = tid & 127, kq2 = (tid >> 7) * 16;
    const float* bs = B + (size_t)(kt + kq2) * N + bn + n;
#pragma unroll
    for (int j = 0; j < 16; j++) rb[j] = bs[(size_t)j * N];
}

__device__ __forceinline__ void sts_tiles(char* st, int tid, const float* ra, const float* rb)
{
    const int r = tid >> 2, kq = (tid & 3) * 8;
#pragma unroll
    for (int p = 0; p < 2; p++) {
        uint4 hi, lo; cvt8(ra + p * 8, hi, lo);
        const int m = r + p * 64;
        *reinterpret_cast<uint4*>(st + m * HP + kq * 2)         = hi;
        *reinterpret_cast<uint4*>(st + 10240 + m * HP + kq * 2) = lo;
    }
    const int n = tid & 127, kq2 = (tid >> 7) * 16;
    {
        uint4 hi, lo; cvt8(rb, hi, lo);
        *reinterpret_cast<uint4*>(st + 20480 + n * HP + kq2 * 2) = hi;
        *reinterpret_cast<uint4*>(st + 30720 + n * HP + kq2 * 2) = lo;
    }
    {
        uint4 hi, lo; cvt8(rb + 8, hi, lo);
        *reinterpret_cast<uint4*>(st + 20480 + n * HP + (kq2 + 8) * 2) = hi;
        *reinterpret_cast<uint4*>(st + 30720 + n * HP + (kq2 + 8) * 2) = lo;
    }
}

__global__ __launch_bounds__(256) void hgemm(
    const float* __restrict__ A, const float* __restrict__ B,
    float* __restrict__ C, int M, int N, int K)
{
    extern __shared__ char sm[];
    const uint32_t sbase = smem_u32(sm);
    const int tid = threadIdx.x, lane = tid & 31, w = tid >> 5;
    const int wm = (w >> 2) * 64, wn = (w & 3) * 32;
    const int bm = blockIdx.y * 128, bn = blockIdx.x * 128;

    float acc[4][4][4];
#pragma unroll
    for (int i = 0; i < 4; i++)
#pragma unroll
        for (int j = 0; j < 4; j++)
#pragma unroll
            for (int q = 0; q < 4; q++) acc[i][j][q] = 0.f;

    float ra[16], rb[16];
    const int niter = K >> 5;

    // ldmatrix per-lane address offsets
    const int bl = lane & 15;
    const uint32_t a_lane = (uint32_t)((wm + (lane & 15)) * HP + ((lane >> 4) << 4));
    const uint32_t b_lane = (uint32_t)((wn + (bl & 7)) * HP + ((bl >> 3) << 4));

    ldg_tiles(A, B, bm, bn, 0, N, K, tid, ra, rb);
    sts_tiles(sm, tid, ra, rb);
    __syncthreads();

    for (int it = 0; it < niter; ++it) {
        if (it + 1 < niter)
            ldg_tiles(A, B, bm, bn, (it + 1) << 5, N, K, tid, ra, rb);

        const uint32_t sA   = sbase + (uint32_t)(it & 1) * HSTAGE;
        const uint32_t sAlo = sA + 10240;
        const uint32_t sBhi = sA + 20480;
        const uint32_t sBlo = sA + 30720;
#pragma unroll
        for (int ks = 0; ks < 32; ks += 16) {
            uint32_t bh[4][2], blo_[4][2];
            const uint32_t bo = b_lane + ks * 2;
#pragma unroll
            for (int ni = 0; ni < 4; ni++) {
                ldmx2(bh[ni],   sBhi + bo + ni * (8 * HP));
                ldmx2(blo_[ni], sBlo + bo + ni * (8 * HP));
            }
            const uint32_t ao = a_lane + ks * 2;
#pragma unroll
            for (int mi = 0; mi < 4; mi++) {
                uint32_t ah[4], al_[4];
                ldmx4(ah,  sA   + ao + mi * (16 * HP));
                ldmx4(al_, sAlo + ao + mi * (16 * HP));
#pragma unroll
                for (int ni = 0; ni < 4; ni++) {
                    mma16816(acc[mi][ni], ah,  bh[ni]);
                    mma16816(acc[mi][ni], al_, bh[ni]);
                    mma16816(acc[mi][ni], ah,  blo_[ni]);
                }
            }
        }

        if (it + 1 < niter)
            sts_tiles(sm + ((it + 1) & 1) * HSTAGE, tid, ra, rb);
        __syncthreads();
    }

    // epilogue
#pragma unroll
    for (int mi = 0; mi < 4; mi++) {
        const int row = bm + wm + mi * 16 + (lane >> 2);
#pragma unroll
        for (int ni = 0; ni < 4; ni++) {
            const int col = bn + wn + ni * 8 + (lane & 3) * 2;
            float2 v0; v0.x = acc[mi][ni][0]; v0.y = acc[mi][ni][1];
            float2 v1; v1.x = acc[mi][ni][2]; v1.y = acc[mi][ni][3];
            *reinterpret_cast<float2*>(C + (size_t)row * N + col)       = v0;
            *reinterpret_cast<float2*>(C + (size_t)(row + 8) * N + col) = v1;
        }
    }
}

// ---------------- tiny-N GEMM (N=6): one block per row ----------------
__global__ __launch_bounds__(128) void gemm6(
    const float* __restrict__ A, const float* __restrict__ W,
    float* __restrict__ C, int K)
{
    __shared__ float red[128 * 8];
    const int r = blockIdx.x, tid = threadIdx.x;
    float acc[6] = {0.f, 0.f, 0.f, 0.f, 0.f, 0.f};
    const float* arow = A + (size_t)r * K;
    for (int k = tid; k < K; k += 128) {
        float a = arow[k];
#pragma unroll
        for (int j = 0; j < 6; j++) acc[j] = fmaf(a, W[k * 6 + j], acc[j]);
    }
#pragma unroll
    for (int j = 0; j < 6; j++) red[tid * 8 + j] = acc[j];
    __syncthreads();
    for (int s = 64; s > 0; s >>= 1) {
        if (tid < s) {
#pragma unroll
            for (int j = 0; j < 6; j++) red[tid * 8 + j] += red[(tid + s) * 8 + j];
        }
        __syncthreads();
    }
    if (tid < 6) C[r * 6 + tid] = red[tid];
}

// ---------------- activations for beta / g ----------------
__global__ void act_bg(
    const float* __restrict__ bx0, const float* __restrict__ bx1,
    const float* __restrict__ ax,  const float* __restrict__ A_log,
    const float* __restrict__ dtb, float* __restrict__ be0,
    float* __restrict__ be1, float* __restrict__ gd)
{
    int i = blockIdx.x * blockDim.x + threadIdx.x;
    if (i >= RROWS * HH) return;
    int hh = i % HH;
    be0[i] = 1.f / (1.f + expf(-bx0[i]));
    be1[i] = 1.f / (1.f + expf(-bx1[i]));
    float z = ax[i] + dtb[hh];
    float sp = (z > 20.f) ? z : log1pf(expf(z));
    gd[i] = -expf(A_log[hh]) * sp;
}

// ---------------- conv(4) + SiLU + per-head L2 norm (q/k path) ----------------
__global__ __launch_bounds__(256) void conv_silu_norm(
    const float* __restrict__ Z, const float* __restrict__ W,
    float* __restrict__ Out, float outscale)
{
    const int r = blockIdx.x, h = blockIdx.y, tid = threadIdx.x;
    const int b = r >> 10, t = r & 1023;
    const int c = h * DK + tid;
    float acc = 0.f;
#pragma unroll
    for (int j = 0; j < 4; j++) {
        int tj = t - 3 + j;
        if (tj >= 0) acc = fmaf(Z[(size_t)(b * TLEN + tj) * KEY_DIM + c], W[c * 4 + j], acc);
    }
    float y = acc / (1.f + expf(-acc));   // silu
    __shared__ float sred[256];
    sred[tid] = y * y;
    __syncthreads();
    for (int s = 128; s > 0; s >>= 1) {
        if (tid < s) sred[tid] += sred[tid + s];
        __syncthreads();
    }
    float scale = rsqrtf(sred[0] + 1e-12f) * outscale;
    Out[(size_t)r * KEY_DIM + c] = y * scale;
}

// ---------------- conv(4) + SiLU for v path ----------------
__global__ void conv_silu_v(
    const float* __restrict__ Z, const float* __restrict__ W,
    float* __restrict__ Out)
{
    int idx = blockIdx.x * blockDim.x + threadIdx.x;
    if (idx >= RROWS * VAL_DIM) return;
    int c = idx % VAL_DIM;
    int r = idx / VAL_DIM;
    int b = r >> 10, t = r & 1023;
    float acc = 0.f;
#pragma unroll
    for (int j = 0; j < 4; j++) {
        int tj = t - 3 + j;
        if (tj >= 0) acc = fmaf(Z[(size_t)(b * TLEN + tj) * VAL_DIM + c], W[c * 4 + j], acc);
    }
    Out[idx] = acc / (1.f + expf(-acc));
}

// ---------------- packed f32x2 helpers ----------------
union F2U { float2 f; unsigned long long u; };

__device__ __forceinline__ F2U ffma2(F2U a, F2U b, F2U c) {
    F2U r;
    asm("fma.rn.f32x2 %0, %1, %2, %3;" : "=l"(r.u) : "l"(a.u), "l"(b.u), "l"(c.u));
    return r;
}
__device__ __forceinline__ F2U fmul2(F2U a, F2U b) {
    F2U r;
    asm("mul.rn.f32x2 %0, %1, %2;" : "=l"(r.u) : "l"(a.u), "l"(b.u));
    return r;
}
__device__ __forceinline__ float hsum16(float v) {
    v += __shfl_xor_sync(0xffffffffu, v, 8);
    v += __shfl_xor_sync(0xffffffffu, v, 4);
    v += __shfl_xor_sync(0xffffffffu, v, 2);
    v += __shfl_xor_sync(0xffffffffu, v, 1);
    return v;
}

// ---------------- gated delta-rule recurrence ----------------
__global__ __launch_bounds__(256, 3) void delta_recur(
    const float* __restrict__ Qn,  const float* __restrict__ Kn0, const float* __restrict__ Kn1,
    const float* __restrict__ Vs0, const float* __restrict__ Vs1,
    const float* __restrict__ Be0, const float* __restrict__ Be1,
    const float* __restrict__ Gd,  float* __restrict__ O)
{
    const int bh = blockIdx.x;
    const int b = bh / HH, h = bh % HH;
    const int tid = threadIdx.x;
    const int warp = tid >> 5, lane = tid & 31;
    const int half = lane >> 4, l0 = lane & 15;
    const int col = blockIdx.y * 16 + warp * 2 + half;

    __shared__ __align__(16) float sk0[256], sk1[256], sq[256];
    __shared__ float ssc[4];

    F2U S[8];
#pragma unroll
    for (int j = 0; j < 8; j++) S[j].u = 0ull;

    const float2* pk0 = reinterpret_cast<const float2*>(sk0);
    const float2* pk1 = reinterpret_cast<const float2*>(sk1);
    const float2* pq  = reinterpret_cast<const float2*>(sq);

    for (int t = 0; t < TLEN; t++) {
        const int r = b * TLEN + t;
        const size_t kbase = (size_t)r * KEY_DIM + h * DK;
        __syncthreads();
        sk0[tid] = Kn0[kbase + tid];
        sk1[tid] = Kn1[kbase + tid];
        sq [tid] = Qn [kbase + tid];
        if (tid == 0) {
            int gi = r * HH + h;
            ssc[0] = Gd[gi]; ssc[1] = Be0[gi]; ssc[2] = Be1[gi];
        }
        __syncthreads();
        const float decay = expf(ssc[0]);
        const float bb0 = ssc[1], bb1 = ssc[2];
        const size_t vbase = (size_t)r * VAL_DIM + h * DV + col;
        const float v0 = Vs0[vbase];
        const float v1 = Vs1[vbase];

        F2U rk[8], acc;
#pragma unroll
        for (int j = 0; j < 8; j++) rk[j].f = pk0[j * 16 + l0];
        acc.u = 0ull;
#pragma unroll
        for (int j = 0; j < 8; j++) acc = ffma2(rk[j], S[j], acc);
        float dot0 = hsum16(acc.f.x + acc.f.y) * decay;
        float u0 = (v0 - dot0) * bb0;
        F2U dec2; dec2.f = make_float2(decay, decay);
        F2U u0v;  u0v.f  = make_float2(u0, u0);
#pragma unroll
        for (int j = 0; j < 8; j++) S[j] = ffma2(S[j], dec2, fmul2(rk[j], u0v));
#pragma unroll
        for (int j = 0; j < 8; j++) rk[j].f = pk1[j * 16 + l0];
        acc.u = 0ull;
#pragma unroll
        for (int j = 0; j < 8; j++) acc = ffma2(rk[j], S[j], acc);
        float dot1 = hsum16(acc.f.x + acc.f.y);
        float u1 = (v1 - dot1) * bb1;
        F2U u1v; u1v.f = make_float2(u1, u1);
#pragma unroll
        for (int j = 0; j < 8; j++) S[j] = ffma2(rk[j], u1v, S[j]);
#pragma unroll
        for (int j = 0; j < 8; j++) rk[j].f = pq[j * 16 + l0];
        acc.u = 0ull;
#pragma unroll
        for (int j = 0; j < 8; j++) acc = ffma2(rk[j], S[j], acc);
        float outv = hsum16(acc.f.x + acc.f.y);
        if (l0 == 0) O[(size_t)(r * HH + h) * DV + col] = outv;
    }
}

// ---------------- RMS norm over DV + gated SiLU ----------------
__global__ __launch_bounds__(256) void rms_gate(
    const float* __restrict__ Ob, const float* __restrict__ Gx,
    const float* __restrict__ onw, float* __restrict__ Y)
{
    const int r = blockIdx.x, h = blockIdx.y, tid = threadIdx.x;
    const size_t base = (size_t)(r * HH + h) * DV;
    float o0 = Ob[base + tid], o1 = Ob[base + tid + 256];
    __shared__ float sred[256];
    sred[tid] = o0 * o0 + o1 * o1;
    __syncthreads();
    for (int s = 128; s > 0; s >>= 1) {
        if (tid < s) sred[tid] += sred[tid + s];
        __syncthreads();
    }
    float scale = rsqrtf(sred[0] * (1.f / 512.f) + 1e-5f);
    float g0 = Gx[base + tid], g1 = Gx[base + tid + 256];
    Y[base + tid]       = o0 * scale * onw[tid]       * (g0 / (1.f + expf(-g0)));
    Y[base + tid + 256] = o1 * scale * onw[tid + 256] * (g1 / (1.f + expf(-g1)));
}

// ---------------- launch ----------------
extern "C" void kernel_launch(void* const* d_in, const int* in_sizes, int n_in,
                              void* d_out, int out_size)
{
    const float* x     = (const float*)d_in[0];
    const float* q_w   = (const float*)d_in[1];
    const float* k_ws  = (const float*)d_in[2];
    const float* v_ws  = (const float*)d_in[3];
    const float* b_ws  = (const float*)d_in[4];
    const float* a_w   = (const float*)d_in[5];
    const float* g_w   = (const float*)d_in[6];
    const float* o_w   = (const float*)d_in[7];
    const float* qcw   = (const float*)d_in[8];
    const float* kcw   = (const float*)d_in[9];
    const float* vcw   = (const float*)d_in[10];
    const float* A_log = (const float*)d_in[11];
    const float* dtb   = (const float*)d_in[12];
    const float* onw   = (const float*)d_in[13];
    float* out = (float*)d_out;

    float *qx, *kx0, *kx1, *vx0, *vx1, *gate, *qn, *kn0, *kn1, *vs0, *vs1, *ob, *yb;
    float *bx0, *bx1, *ax, *be0, *be1, *gd;
    cudaGetSymbolAddress((void**)&qx,  g_qx);
    cudaGetSymbolAddress((void**)&kx0, g_kx0);
    cudaGetSymbolAddress((void**)&kx1, g_kx1);
    cudaGetSymbolAddress((void**)&vx0, g_vx0);
    cudaGetSymbolAddress((void**)&vx1, g_vx1);
    cudaGetSymbolAddress((void**)&gate, g_gate);
    cudaGetSymbolAddress((void**)&qn,  g_qn);
    cudaGetSymbolAddress((void**)&kn0, g_kn0);
    cudaGetSymbolAddress((void**)&kn1, g_kn1);
    cudaGetSymbolAddress((void**)&vs0, g_vs0);
    cudaGetSymbolAddress((void**)&vs1, g_vs1);
    cudaGetSymbolAddress((void**)&ob,  g_ob);
    cudaGetSymbolAddress((void**)&yb,  g_yb);
    cudaGetSymbolAddress((void**)&bx0, g_bx0);
    cudaGetSymbolAddress((void**)&bx1, g_bx1);
    cudaGetSymbolAddress((void**)&ax,  g_ax);
    cudaGetSymbolAddress((void**)&be0, g_be0);
    cudaGetSymbolAddress((void**)&be1, g_be1);
    cudaGetSymbolAddress((void**)&gd,  g_gd);

    cudaFuncSetAttribute(hgemm, cudaFuncAttributeMaxDynamicSharedMemorySize, HSMEM);

    // 1) projections (mma.sync bf16x3)
    hgemm<<<dim3(KEY_DIM/128, RROWS/128), 256, HSMEM>>>(x, q_w, qx, RROWS, KEY_DIM, HID);
    hgemm<<<dim3(KEY_DIM/128, RROWS/128), 256, HSMEM>>>(x, k_ws, kx0, RROWS, KEY_DIM, HID);
    hgemm<<<dim3(KEY_DIM/128, RROWS/128), 256, HSMEM>>>(x, k_ws + (size_t)HID*KEY_DIM, kx1, RROWS, KEY_DIM, HID);
    hgemm<<<dim3(VAL_DIM/128, RROWS/128), 256, HSMEM>>>(x, v_ws, vx0, RROWS, VAL_DIM, HID);
    hgemm<<<dim3(VAL_DIM/128, RROWS/128), 256, HSMEM>>>(x, v_ws + (size_t)HID*VAL_DIM, vx1, RROWS, VAL_DIM, HID);
    hgemm<<<dim3(VAL_DIM/128, RROWS/128), 256, HSMEM>>>(x, g_w, gate, RROWS, VAL_DIM, HID);
    gemm6<<<RROWS, 128>>>(x, b_ws, bx0, HID);
    gemm6<<<RROWS, 128>>>(x, b_ws + (size_t)HID * HH, bx1, HID);
    gemm6<<<RROWS, 128>>>(x, a_w, ax, HID);

    // 2) activations / conv / norms
    act_bg<<<(RROWS * HH + 255) / 256, 256>>>(bx0, bx1, ax, A_log, dtb, be0, be1, gd);
    conv_silu_norm<<<dim3(RROWS, HH), 256>>>(qx,  qcw, qn, 0.0625f);  // * DK^-0.5
    conv_silu_norm<<<dim3(RROWS, HH), 256>>>(kx0, kcw, kn0, 1.f);
    conv_silu_norm<<<dim3(RROWS, HH), 256>>>(kx1, kcw + KEY_DIM * 4, kn1, 1.f);
    conv_silu_v<<<(RROWS * VAL_DIM + 255) / 256, 256>>>(vx0, vcw, vs0);
    conv_silu_v<<<(RROWS * VAL_DIM + 255) / 256, 256>>>(vx1, vcw + VAL_DIM * 4, vs1);

    // 3) sequential gated delta rule
    delta_recur<<<dim3(BSZ * HH, DV / 16), 256>>>(qn, kn0, kn1, vs0, vs1, be0, be1, gd, ob);

    // 4) output norm + gate + final projection
    rms_gate<<<dim3(RROWS, HH), 256>>>(ob, gate, onw, yb);
    hgemm<<<dim3(HID/128, RROWS/128), 256, HSMEM>>>(yb, o_w, out, RROWS, HID, VAL_DIM);
}

// round 7
// speedup vs baseline: 1.8989x; 1.1008x over previous
#include <cuda_runtime.h>
#include <cuda_bf16.h>
#include <cstdint>

// ---------------- problem constants ----------------
#define BSZ 2
#define TLEN 1024
#define HID 2048
#define NHEADS 2
#define HH 6
#define DK 256
#define DV 512
#define KEY_DIM 1536   // HH*DK
#define VAL_DIM 3072   // HH*DV
#define RROWS 2048     // BSZ*TLEN

// concatenated projection layout: [ q | k0 | k1 | v0 | v1 | gate ]
#define PROJ_W 13824
#define OFF_Q  0
#define OFF_K0 1536
#define OFF_K1 3072
#define OFF_V0 4608
#define OFF_V1 7680
#define OFF_G  10752

// ---------------- scratch (static device memory; no allocs) ----------------
__device__ float g_proj[(size_t)RROWS * PROJ_W];
__device__ __nv_bfloat16 g_xhi[(size_t)RROWS * HID];
__device__ __nv_bfloat16 g_xlo[(size_t)RROWS * HID];
__device__ __nv_bfloat16 g_wch[(size_t)HID * PROJ_W];
__device__ __nv_bfloat16 g_wcl[(size_t)HID * PROJ_W];
__device__ __nv_bfloat16 g_owh[(size_t)VAL_DIM * HID];
__device__ __nv_bfloat16 g_owl[(size_t)VAL_DIM * HID];
__device__ __nv_bfloat16 g_ybh[(size_t)RROWS * VAL_DIM];
__device__ __nv_bfloat16 g_ybl[(size_t)RROWS * VAL_DIM];
__device__ float g_qn [RROWS*KEY_DIM];
__device__ float g_kn0[RROWS*KEY_DIM];
__device__ float g_kn1[RROWS*KEY_DIM];
__device__ float g_vs0[RROWS*VAL_DIM];
__device__ float g_vs1[RROWS*VAL_DIM];
__device__ float g_ob [RROWS*VAL_DIM];
__device__ float g_bx0[RROWS*HH];
__device__ float g_bx1[RROWS*HH];
__device__ float g_ax [RROWS*HH];
__device__ float g_be0[RROWS*HH];
__device__ float g_be1[RROWS*HH];
__device__ float g_gd [RROWS*HH];

// ================= helpers =================
__device__ __forceinline__ uint32_t smem_u32(const void* p) {
    uint32_t a;
    asm("{ .reg .u64 t; cvta.to.shared.u64 t, %1; cvt.u32.u64 %0, t; }" : "=r"(a) : "l"(p));
    return a;
}
__device__ __forceinline__ void ldmx4(uint32_t* r, uint32_t addr) {
    asm volatile("ldmatrix.sync.aligned.m8n8.x4.shared.b16 {%0,%1,%2,%3}, [%4];"
        : "=r"(r[0]), "=r"(r[1]), "=r"(r[2]), "=r"(r[3]) : "r"(addr));
}
__device__ __forceinline__ void ldmx2t(uint32_t* r, uint32_t addr) {
    asm volatile("ldmatrix.sync.aligned.m8n8.x2.trans.shared.b16 {%0,%1}, [%2];"
        : "=r"(r[0]), "=r"(r[1]) : "r"(addr));
}
__device__ __forceinline__ void mma16816(float* c, const uint32_t* a, const uint32_t* b) {
    asm volatile(
        "mma.sync.aligned.m16n8k16.row.col.f32.bf16.bf16.f32 "
        "{%0,%1,%2,%3}, {%4,%5,%6,%7}, {%8,%9}, {%0,%1,%2,%3};"
        : "+f"(c[0]), "+f"(c[1]), "+f"(c[2]), "+f"(c[3])
        : "r"(a[0]), "r"(a[1]), "r"(a[2]), "r"(a[3]), "r"(b[0]), "r"(b[1]));
}
__device__ __forceinline__ void cpa16(uint32_t dst, const void* src) {
    asm volatile("cp.async.cg.shared.global [%0], [%1], 16;" :: "r"(dst), "l"(src));
}

// ================= fp32 -> bf16 hi/lo split =================
__global__ void cvt_split(const float* __restrict__ s,
                          __nv_bfloat16* __restrict__ h, __nv_bfloat16* __restrict__ l, int n)
{
    int i = (blockIdx.x * blockDim.x + threadIdx.x) * 4;
    if (i >= n) return;
    float4 v = *reinterpret_cast<const float4*>(s + i);
    __nv_bfloat162 h0 = __floats2bfloat162_rn(v.x, v.y);
    __nv_bfloat162 h1 = __floats2bfloat162_rn(v.z, v.w);
    __nv_bfloat162 l0 = __floats2bfloat162_rn(v.x - __low2float(h0), v.y - __high2float(h0));
    __nv_bfloat162 l1 = __floats2bfloat162_rn(v.z - __low2float(h1), v.w - __high2float(h1));
    *reinterpret_cast<__nv_bfloat162*>(h + i)     = h0;
    *reinterpret_cast<__nv_bfloat162*>(h + i + 2) = h1;
    *reinterpret_cast<__nv_bfloat162*>(l + i)     = l0;
    *reinterpret_cast<__nv_bfloat162*>(l + i + 2) = l1;
}

// weight [K][Ns] -> concatenated [K][PROJ_W] at column offset
__global__ void cvt_wcat(const float* __restrict__ s,
                         __nv_bfloat16* __restrict__ h, __nv_bfloat16* __restrict__ l,
                         int Ns, int off, int total)
{
    int i = (blockIdx.x * blockDim.x + threadIdx.x) * 4;
    if (i >= total) return;
    int k = i / Ns, n = i % Ns;
    size_t d = (size_t)k * PROJ_W + off + n;
    float4 v = *reinterpret_cast<const float4*>(s + i);
    __nv_bfloat162 h0 = __floats2bfloat162_rn(v.x, v.y);
    __nv_bfloat162 h1 = __floats2bfloat162_rn(v.z, v.w);
    __nv_bfloat162 l0 = __floats2bfloat162_rn(v.x - __low2float(h0), v.y - __high2float(h0));
    __nv_bfloat162 l1 = __floats2bfloat162_rn(v.z - __low2float(h1), v.w - __high2float(h1));
    *reinterpret_cast<__nv_bfloat162*>(h + d)     = h0;
    *reinterpret_cast<__nv_bfloat162*>(h + d + 2) = h1;
    *reinterpret_cast<__nv_bfloat162*>(l + d)     = l0;
    *reinterpret_cast<__nv_bfloat162*>(l + d + 2) = l1;
}

// ================= bf16x3 HMMA GEMM, cp.async pipelined =================
// C[M,N] = (Ahi+Alo)[M,K] @ (Bhi+Blo)[K,N] (3 passes: hh + lh + hl)
// Tile 128x128, BK=32, 256 threads, double-buffered, 2 CTAs/SM.
// SMEM stage: Ahi[128x80B]=10240 | Alo=10240 | Bhi[32x272B]=8704 | Blo=8704
#define HSTG 37888
#define HSM2 (2 * HSTG)

__device__ __forceinline__ void issue_stage(
    uint32_t st,
    const __nv_bfloat16* __restrict__ Ahi, const __nv_bfloat16* __restrict__ Alo,
    const __nv_bfloat16* __restrict__ Bhi, const __nv_bfloat16* __restrict__ Blo,
    int bm, int bn, int kt, int N, int K, int tid)
{
#pragma unroll
    for (int hq = 0; hq < 2; hq++) {
        int c = tid + hq * 256;
        int m = c >> 2, sl = c & 3;
        size_t so = (size_t)(bm + m) * K + kt + sl * 8;
        uint32_t d = st + m * 80 + sl * 16;
        cpa16(d,          Ahi + so);
        cpa16(d + 10240,  Alo + so);
    }
#pragma unroll
    for (int hq = 0; hq < 2; hq++) {
        int c = tid + hq * 256;
        int k = c >> 4, n8 = c & 15;
        size_t so = (size_t)(kt + k) * N + bn + n8 * 8;
        uint32_t sw = (uint32_t)(((n8 & 8) | ((n8 ^ k) & 7)) * 16);
        uint32_t d = st + 20480 + k * 272 + sw;
        cpa16(d,         Bhi + so);
        cpa16(d + 8704,  Blo + so);
    }
}

__global__ void __launch_bounds__(256, 2) hgemm2(
    const __nv_bfloat16* __restrict__ Ahi, const __nv_bfloat16* __restrict__ Alo,
    const __nv_bfloat16* __restrict__ Bhi, const __nv_bfloat16* __restrict__ Blo,
    float* __restrict__ C, int M, int N, int K)
{
    extern __shared__ char sm2[];
    const uint32_t sbase = smem_u32(sm2);
    const int tid = threadIdx.x, lane = tid & 31, w = tid >> 5;
    const int wm = (w >> 2) * 64, wn = (w & 3) * 32;
    const int bm = blockIdx.y * 128, bn = blockIdx.x * 128;
    const int wslot = (w & 3) * 4;

    float acc[4][4][4];
#pragma unroll
    for (int i = 0; i < 4; i++)
#pragma unroll
        for (int j = 0; j < 4; j++)
#pragma unroll
            for (int q = 0; q < 4; q++) acc[i][j][q] = 0.f;

    const int niter = K >> 5;
    const uint32_t a_lane = (uint32_t)((wm + (lane & 15)) * 80 + ((lane >> 4) << 4));

    issue_stage(sbase, Ahi, Alo, Bhi, Blo, bm, bn, 0, N, K, tid);
    asm volatile("cp.async.commit_group;" ::: "memory");

    for (int it = 0; it < niter; ++it) {
        if (it + 1 < niter) {
            issue_stage(sbase + (uint32_t)((it + 1) & 1) * HSTG,
                        Ahi, Alo, Bhi, Blo, bm, bn, (it + 1) << 5, N, K, tid);
            asm volatile("cp.async.commit_group;" ::: "memory");
            asm volatile("cp.async.wait_group 1;" ::: "memory");
        } else {
            asm volatile("cp.async.wait_group 0;" ::: "memory");
        }
        __syncthreads();

        const uint32_t sA   = sbase + (uint32_t)(it & 1) * HSTG;
        const uint32_t sAlo = sA + 10240;
        const uint32_t sB   = sA + 20480;
        const uint32_t sBlo = sA + 29184;

#pragma unroll
        for (int ks = 0; ks < 32; ks += 16) {
            const int klane = ks + (lane & 15);
            const uint32_t bro = (uint32_t)(klane * 272);
            uint32_t bh[4][2], bl[4][2];
#pragma unroll
            for (int ni = 0; ni < 4; ni++) {
                const int slot = wslot + ni;
                const uint32_t off = bro + (uint32_t)((((slot ^ klane) & 7) | (slot & 8)) * 16);
                ldmx2t(bh[ni], sB + off);
                ldmx2t(bl[ni], sBlo + off);
            }
            const uint32_t ao = a_lane + ks * 2;
#pragma unroll
            for (int mi = 0; mi < 4; mi++) {
                uint32_t ah[4], al_[4];
                ldmx4(ah,  sA   + ao + mi * (16 * 80));
                ldmx4(al_, sAlo + ao + mi * (16 * 80));
#pragma unroll
                for (int ni = 0; ni < 4; ni++) {
                    mma16816(acc[mi][ni], ah,  bh[ni]);
                    mma16816(acc[mi][ni], al_, bh[ni]);
                    mma16816(acc[mi][ni], ah,  bl[ni]);
                }
            }
        }
        __syncthreads();
    }

    // epilogue
#pragma unroll
    for (int mi = 0; mi < 4; mi++) {
        const int row = bm + wm + mi * 16 + (lane >> 2);
#pragma unroll
        for (int ni = 0; ni < 4; ni++) {
            const int col = bn + wn + ni * 8 + (lane & 3) * 2;
            float2 v0; v0.x = acc[mi][ni][0]; v0.y = acc[mi][ni][1];
            float2 v1; v1.x = acc[mi][ni][2]; v1.y = acc[mi][ni][3];
            *reinterpret_cast<float2*>(C + (size_t)row * N + col)       = v0;
            *reinterpret_cast<float2*>(C + (size_t)(row + 8) * N + col) = v1;
        }
    }
}

// ---------------- tiny-N GEMM (N=6): one block per row ----------------
__global__ __launch_bounds__(128) void gemm6(
    const float* __restrict__ A, const float* __restrict__ W,
    float* __restrict__ C, int K)
{
    __shared__ float red[128 * 8];
    const int r = blockIdx.x, tid = threadIdx.x;
    float acc[6] = {0.f, 0.f, 0.f, 0.f, 0.f, 0.f};
    const float* arow = A + (size_t)r * K;
    for (int k = tid; k < K; k += 128) {
        float a = arow[k];
#pragma unroll
        for (int j = 0; j < 6; j++) acc[j] = fmaf(a, W[k * 6 + j], acc[j]);
    }
#pragma unroll
    for (int j = 0; j < 6; j++) red[tid * 8 + j] = acc[j];
    __syncthreads();
    for (int s = 64; s > 0; s >>= 1) {
        if (tid < s) {
#pragma unroll
            for (int j = 0; j < 6; j++) red[tid * 8 + j] += red[(tid + s) * 8 + j];
        }
        __syncthreads();
    }
    if (tid < 6) C[r * 6 + tid] = red[tid];
}

// ---------------- activations for beta / g ----------------
__global__ void act_bg(
    const float* __restrict__ bx0, const float* __restrict__ bx1,
    const float* __restrict__ ax,  const float* __restrict__ A_log,
    const float* __restrict__ dtb, float* __restrict__ be0,
    float* __restrict__ be1, float* __restrict__ gd)
{
    int i = blockIdx.x * blockDim.x + threadIdx.x;
    if (i >= RROWS * HH) return;
    int hh = i % HH;
    be0[i] = 1.f / (1.f + expf(-bx0[i]));
    be1[i] = 1.f / (1.f + expf(-bx1[i]));
    float z = ax[i] + dtb[hh];
    float sp = (z > 20.f) ? z : log1pf(expf(z));
    gd[i] = -expf(A_log[hh]) * sp;
}

// ---------------- conv(4) + SiLU + per-head L2 norm (q/k path) ----------------
// reads from strided (concatenated) projection buffer
__global__ __launch_bounds__(256) void conv_silu_norm(
    const float* __restrict__ Z, int zoff, const float* __restrict__ W,
    float* __restrict__ Out, float outscale)
{
    const int r = blockIdx.x, h = blockIdx.y, tid = threadIdx.x;
    const int b = r >> 10, t = r & 1023;
    const int c = h * DK + tid;
    float acc = 0.f;
#pragma unroll
    for (int j = 0; j < 4; j++) {
        int tj = t - 3 + j;
        if (tj >= 0) acc = fmaf(Z[(size_t)(b * TLEN + tj) * PROJ_W + zoff + c], W[c * 4 + j], acc);
    }
    float y = acc / (1.f + expf(-acc));   // silu
    __shared__ float sred[256];
    sred[tid] = y * y;
    __syncthreads();
    for (int s = 128; s > 0; s >>= 1) {
        if (tid < s) sred[tid] += sred[tid + s];
        __syncthreads();
    }
    float scale = rsqrtf(sred[0] + 1e-12f) * outscale;
    Out[(size_t)r * KEY_DIM + c] = y * scale;
}

// ---------------- conv(4) + SiLU for v path ----------------
__global__ void conv_silu_v(
    const float* __restrict__ Z, int zoff, const float* __restrict__ W,
    float* __restrict__ Out)
{
    int idx = blockIdx.x * blockDim.x + threadIdx.x;
    if (idx >= RROWS * VAL_DIM) return;
    int c = idx % VAL_DIM;
    int r = idx / VAL_DIM;
    int b = r >> 10, t = r & 1023;
    float acc = 0.f;
#pragma unroll
    for (int j = 0; j < 4; j++) {
        int tj = t - 3 + j;
        if (tj >= 0) acc = fmaf(Z[(size_t)(b * TLEN + tj) * PROJ_W + zoff + c], W[c * 4 + j], acc);
    }
    Out[idx] = acc / (1.f + expf(-acc));
}

// ---------------- packed f32x2 helpers ----------------
union F2U { float2 f; unsigned long long u; };

__device__ __forceinline__ F2U ffma2(F2U a, F2U b, F2U c) {
    F2U r;
    asm("fma.rn.f32x2 %0, %1, %2, %3;" : "=l"(r.u) : "l"(a.u), "l"(b.u), "l"(c.u));
    return r;
}
__device__ __forceinline__ F2U fmul2(F2U a, F2U b) {
    F2U r;
    asm("mul.rn.f32x2 %0, %1, %2;" : "=l"(r.u) : "l"(a.u), "l"(b.u));
    return r;
}
__device__ __forceinline__ float hsum16(float v) {
    v += __shfl_xor_sync(0xffffffffu, v, 8);
    v += __shfl_xor_sync(0xffffffffu, v, 4);
    v += __shfl_xor_sync(0xffffffffu, v, 2);
    v += __shfl_xor_sync(0xffffffffu, v, 1);
    return v;
}

// ---------------- gated delta-rule recurrence ----------------
__global__ __launch_bounds__(256, 3) void delta_recur(
    const float* __restrict__ Qn,  const float* __restrict__ Kn0, const float* __restrict__ Kn1,
    const float* __restrict__ Vs0, const float* __restrict__ Vs1,
    const float* __restrict__ Be0, const float* __restrict__ Be1,
    const float* __restrict__ Gd,  float* __restrict__ O)
{
    const int bh = blockIdx.x;
    const int b = bh / HH, h = bh % HH;
    const int tid = threadIdx.x;
    const int warp = tid >> 5, lane = tid & 31;
    const int half = lane >> 4, l0 = lane & 15;
    const int col = blockIdx.y * 16 + warp * 2 + half;

    __shared__ __align__(16) float sk0[256], sk1[256], sq[256];
    __shared__ float ssc[4];

    F2U S[8];
#pragma unroll
    for (int j = 0; j < 8; j++) S[j].u = 0ull;

    const float2* pk0 = reinterpret_cast<const float2*>(sk0);
    const float2* pk1 = reinterpret_cast<const float2*>(sk1);
    const float2* pq  = reinterpret_cast<const float2*>(sq);

    for (int t = 0; t < TLEN; t++) {
        const int r = b * TLEN + t;
        const size_t kbase = (size_t)r * KEY_DIM + h * DK;
        __syncthreads();
        sk0[tid] = Kn0[kbase + tid];
        sk1[tid] = Kn1[kbase + tid];
        sq [tid] = Qn [kbase + tid];
        if (tid == 0) {
            int gi = r * HH + h;
            ssc[0] = Gd[gi]; ssc[1] = Be0[gi]; ssc[2] = Be1[gi];
        }
        __syncthreads();
        const float decay = expf(ssc[0]);
        const float bb0 = ssc[1], bb1 = ssc[2];
        const size_t vbase = (size_t)r * VAL_DIM + h * DV + col;
        const float v0 = Vs0[vbase];
        const float v1 = Vs1[vbase];

        F2U rk[8], acc;
#pragma unroll
        for (int j = 0; j < 8; j++) rk[j].f = pk0[j * 16 + l0];
        acc.u = 0ull;
#pragma unroll
        for (int j = 0; j < 8; j++) acc = ffma2(rk[j], S[j], acc);
        float dot0 = hsum16(acc.f.x + acc.f.y) * decay;
        float u0 = (v0 - dot0) * bb0;
        F2U dec2; dec2.f = make_float2(decay, decay);
        F2U u0v;  u0v.f  = make_float2(u0, u0);
#pragma unroll
        for (int j = 0; j < 8; j++) S[j] = ffma2(S[j], dec2, fmul2(rk[j], u0v));
#pragma unroll
        for (int j = 0; j < 8; j++) rk[j].f = pk1[j * 16 + l0];
        acc.u = 0ull;
#pragma unroll
        for (int j = 0; j < 8; j++) acc = ffma2(rk[j], S[j], acc);
        float dot1 = hsum16(acc.f.x + acc.f.y);
        float u1 = (v1 - dot1) * bb1;
        F2U u1v; u1v.f = make_float2(u1, u1);
#pragma unroll
        for (int j = 0; j < 8; j++) S[j] = ffma2(rk[j], u1v, S[j]);
#pragma unroll
        for (int j = 0; j < 8; j++) rk[j].f = pq[j * 16 + l0];
        acc.u = 0ull;
#pragma unroll
        for (int j = 0; j < 8; j++) acc = ffma2(rk[j], S[j], acc);
        float outv = hsum16(acc.f.x + acc.f.y);
        if (l0 == 0) O[(size_t)(r * HH + h) * DV + col] = outv;
    }
}

// ---------------- RMS norm over DV + gated SiLU -> bf16 hi/lo ----------------
__global__ __launch_bounds__(256) void rms_gate(
    const float* __restrict__ Ob, const float* __restrict__ Gx,
    const float* __restrict__ onw,
    __nv_bfloat16* __restrict__ Yh, __nv_bfloat16* __restrict__ Yl)
{
    const int r = blockIdx.x, h = blockIdx.y, tid = threadIdx.x;
    const size_t base = (size_t)(r * HH + h) * DV;
    const size_t gbase = (size_t)r * PROJ_W + OFF_G + h * DV;
    float o0 = Ob[base + tid], o1 = Ob[base + tid + 256];
    __shared__ float sred[256];
    sred[tid] = o0 * o0 + o1 * o1;
    __syncthreads();
    for (int s = 128; s > 0; s >>= 1) {
        if (tid < s) sred[tid] += sred[tid + s];
        __syncthreads();
    }
    float scale = rsqrtf(sred[0] * (1.f / 512.f) + 1e-5f);
    float g0 = Gx[gbase + tid], g1 = Gx[gbase + tid + 256];
    float y0 = o0 * scale * onw[tid]       * (g0 / (1.f + expf(-g0)));
    float y1 = o1 * scale * onw[tid + 256] * (g1 / (1.f + expf(-g1)));
    __nv_bfloat16 h0 = __float2bfloat16_rn(y0);
    __nv_bfloat16 h1 = __float2bfloat16_rn(y1);
    Yh[base + tid]       = h0;
    Yh[base + tid + 256] = h1;
    Yl[base + tid]       = __float2bfloat16_rn(y0 - __bfloat162float(h0));
    Yl[base + tid + 256] = __float2bfloat16_rn(y1 - __bfloat162float(h1));
}

// ---------------- launch ----------------
extern "C" void kernel_launch(void* const* d_in, const int* in_sizes, int n_in,
                              void* d_out, int out_size)
{
    const float* x     = (const float*)d_in[0];
    const float* q_w   = (const float*)d_in[1];
    const float* k_ws  = (const float*)d_in[2];
    const float* v_ws  = (const float*)d_in[3];
    const float* b_ws  = (const float*)d_in[4];
    const float* a_w   = (const float*)d_in[5];
    const float* g_w   = (const float*)d_in[6];
    const float* o_w   = (const float*)d_in[7];
    const float* qcw   = (const float*)d_in[8];
    const float* kcw   = (const float*)d_in[9];
    const float* vcw   = (const float*)d_in[10];
    const float* A_log = (const float*)d_in[11];
    const float* dtb   = (const float*)d_in[12];
    const float* onw   = (const float*)d_in[13];
    float* out = (float*)d_out;

    float *proj, *qn, *kn0, *kn1, *vs0, *vs1, *ob;
    float *bx0, *bx1, *ax, *be0, *be1, *gd;
    __nv_bfloat16 *xhi, *xlo, *wch, *wcl, *owh, *owl, *ybh, *ybl;
    cudaGetSymbolAddress((void**)&proj, g_proj);
    cudaGetSymbolAddress((void**)&xhi, g_xhi);
    cudaGetSymbolAddress((void**)&xlo, g_xlo);
    cudaGetSymbolAddress((void**)&wch, g_wch);
    cudaGetSymbolAddress((void**)&wcl, g_wcl);
    cudaGetSymbolAddress((void**)&owh, g_owh);
    cudaGetSymbolAddress((void**)&owl, g_owl);
    cudaGetSymbolAddress((void**)&ybh, g_ybh);
    cudaGetSymbolAddress((void**)&ybl, g_ybl);
    cudaGetSymbolAddress((void**)&qn,  g_qn);
    cudaGetSymbolAddress((void**)&kn0, g_kn0);
    cudaGetSymbolAddress((void**)&kn1, g_kn1);
    cudaGetSymbolAddress((void**)&vs0, g_vs0);
    cudaGetSymbolAddress((void**)&vs1, g_vs1);
    cudaGetSymbolAddress((void**)&ob,  g_ob);
    cudaGetSymbolAddress((void**)&bx0, g_bx0);
    cudaGetSymbolAddress((void**)&bx1, g_bx1);
    cudaGetSymbolAddress((void**)&ax,  g_ax);
    cudaGetSymbolAddress((void**)&be0, g_be0);
    cudaGetSymbolAddress((void**)&be1, g_be1);
    cudaGetSymbolAddress((void**)&gd,  g_gd);

    cudaFuncSetAttribute(hgemm2, cudaFuncAttributeMaxDynamicSharedMemorySize, HSM2);

    // 0) fp32 -> bf16 hi/lo splits
    {
        int n = RROWS * HID;
        cvt_split<<<(n/4 + 255)/256, 256>>>(x, xhi, xlo, n);
    }
    {
        int t;
        t = HID * KEY_DIM;
        cvt_wcat<<<(t/4 + 255)/256, 256>>>(q_w,                          wch, wcl, KEY_DIM, OFF_Q,  t);
        cvt_wcat<<<(t/4 + 255)/256, 256>>>(k_ws,                         wch, wcl, KEY_DIM, OFF_K0, t);
        cvt_wcat<<<(t/4 + 255)/256, 256>>>(k_ws + (size_t)HID*KEY_DIM,   wch, wcl, KEY_DIM, OFF_K1, t);
        t = HID * VAL_DIM;
        cvt_wcat<<<(t/4 + 255)/256, 256>>>(v_ws,                         wch, wcl, VAL_DIM, OFF_V0, t);
        cvt_wcat<<<(t/4 + 255)/256, 256>>>(v_ws + (size_t)HID*VAL_DIM,   wch, wcl, VAL_DIM, OFF_V1, t);
        cvt_wcat<<<(t/4 + 255)/256, 256>>>(g_w,                          wch, wcl, VAL_DIM, OFF_G,  t);
    }
    {
        int n = VAL_DIM * HID;
        cvt_split<<<(n/4 + 255)/256, 256>>>(o_w, owh, owl, n);
    }

    // 1) merged projection GEMM + tiny projections
    hgemm2<<<dim3(PROJ_W/128, RROWS/128), 256, HSM2>>>(xhi, xlo, wch, wcl, proj, RROWS, PROJ_W, HID);
    gemm6<<<RROWS, 128>>>(x, b_ws, bx0, HID);
    gemm6<<<RROWS, 128>>>(x, b_ws + (size_t)HID * HH, bx1, HID);
    gemm6<<<RROWS, 128>>>(x, a_w, ax, HID);

    // 2) activations / conv / norms
    act_bg<<<(RROWS * HH + 255) / 256, 256>>>(bx0, bx1, ax, A_log, dtb, be0, be1, gd);
    conv_silu_norm<<<dim3(RROWS, HH), 256>>>(proj, OFF_Q,  qcw, qn, 0.0625f);  // * DK^-0.5
    conv_silu_norm<<<dim3(RROWS, HH), 256>>>(proj, OFF_K0, kcw, kn0, 1.f);
    conv_silu_norm<<<dim3(RROWS, HH), 256>>>(proj, OFF_K1, kcw + KEY_DIM * 4, kn1, 1.f);
    conv_silu_v<<<(RROWS * VAL_DIM + 255) / 256, 256>>>(proj, OFF_V0, vcw, vs0);
    conv_silu_v<<<(RROWS * VAL_DIM + 255) / 256, 256>>>(proj, OFF_V1, vcw + VAL_DIM * 4, vs1);

    // 3) sequential gated delta rule
    delta_recur<<<dim3(BSZ * HH, DV / 16), 256>>>(qn, kn0, kn1, vs0, vs1, be0, be1, gd, ob);

    // 4) output norm + gate (emits bf16 hi/lo) + final projection
    rms_gate<<<dim3(RROWS, HH), 256>>>(ob, proj, onw, ybh, ybl);
    hgemm2<<<dim3(HID/128, RROWS/128), 256, HSM2>>>(ybh, ybl, owh, owl, out, RROWS, HID, VAL_DIM);
}

// round 9
// speedup vs baseline: 2.3246x; 1.2241x over previous
#include <cuda_runtime.h>
#include <cuda_bf16.h>
#include <cstdint>

// ---------------- problem constants ----------------
#define BSZ 2
#define TLEN 1024
#define HID 2048
#define NHEADS 2
#define HH 6
#define DK 256
#define DV 512
#define KEY_DIM 1536   // HH*DK
#define VAL_DIM 3072   // HH*DV
#define RROWS 2048     // BSZ*TLEN

// concatenated projection layout: [ q | k0 | k1 | v0 | v1 | gate ]
#define PROJ_W 13824
#define OFF_Q  0
#define OFF_K0 1536
#define OFF_K1 3072
#define OFF_V0 4608
#define OFF_V1 7680
#define OFF_G  10752

// ---------------- scratch (static device memory; no allocs) ----------------
__device__ float g_proj[(size_t)RROWS * PROJ_W];
__device__ __nv_bfloat16 g_xhi[(size_t)RROWS * HID];
__device__ __nv_bfloat16 g_xlo[(size_t)RROWS * HID];
__device__ __nv_bfloat16 g_wch[(size_t)HID * PROJ_W];
__device__ __nv_bfloat16 g_wcl[(size_t)HID * PROJ_W];
__device__ __nv_bfloat16 g_owh[(size_t)VAL_DIM * HID];
__device__ __nv_bfloat16 g_owl[(size_t)VAL_DIM * HID];
__device__ __nv_bfloat16 g_ybh[(size_t)RROWS * VAL_DIM];
__device__ __nv_bfloat16 g_ybl[(size_t)RROWS * VAL_DIM];
__device__ float g_qn [RROWS*KEY_DIM];
__device__ float g_kn0[RROWS*KEY_DIM];
__device__ float g_kn1[RROWS*KEY_DIM];
__device__ float g_vs0[RROWS*VAL_DIM];
__device__ float g_vs1[RROWS*VAL_DIM];
__device__ float g_ob [RROWS*VAL_DIM];
__device__ float g_be0[RROWS*HH];
__device__ float g_be1[RROWS*HH];
__device__ float g_gd [RROWS*HH];

// ================= helpers =================
__device__ __forceinline__ uint32_t smem_u32(const void* p) {
    uint32_t a;
    asm("{ .reg .u64 t; cvta.to.shared.u64 t, %1; cvt.u32.u64 %0, t; }" : "=r"(a) : "l"(p));
    return a;
}
__device__ __forceinline__ void ldmx4(uint32_t* r, uint32_t addr) {
    asm volatile("ldmatrix.sync.aligned.m8n8.x4.shared.b16 {%0,%1,%2,%3}, [%4];"
        : "=r"(r[0]), "=r"(r[1]), "=r"(r[2]), "=r"(r[3]) : "r"(addr));
}
__device__ __forceinline__ void ldmx2t(uint32_t* r, uint32_t addr) {
    asm volatile("ldmatrix.sync.aligned.m8n8.x2.trans.shared.b16 {%0,%1}, [%2];"
        : "=r"(r[0]), "=r"(r[1]) : "r"(addr));
}
__device__ __forceinline__ void mma16816(float* c, const uint32_t* a, const uint32_t* b) {
    asm volatile(
        "mma.sync.aligned.m16n8k16.row.col.f32.bf16.bf16.f32 "
        "{%0,%1,%2,%3}, {%4,%5,%6,%7}, {%8,%9}, {%0,%1,%2,%3};"
        : "+f"(c[0]), "+f"(c[1]), "+f"(c[2]), "+f"(c[3])
        : "r"(a[0]), "r"(a[1]), "r"(a[2]), "r"(a[3]), "r"(b[0]), "r"(b[1]));
}
__device__ __forceinline__ void cpa16(uint32_t dst, const void* src) {
    asm volatile("cp.async.cg.shared.global [%0], [%1], 16;" :: "r"(dst), "l"(src));
}

// ================= fp32 -> bf16 hi/lo split =================
__global__ void cvt_split(const float* __restrict__ s,
                          __nv_bfloat16* __restrict__ h, __nv_bfloat16* __restrict__ l, int n)
{
    int i = (blockIdx.x * blockDim.x + threadIdx.x) * 4;
    if (i >= n) return;
    float4 v = *reinterpret_cast<const float4*>(s + i);
    __nv_bfloat162 h0 = __floats2bfloat162_rn(v.x, v.y);
    __nv_bfloat162 h1 = __floats2bfloat162_rn(v.z, v.w);
    __nv_bfloat162 l0 = __floats2bfloat162_rn(v.x - __low2float(h0), v.y - __high2float(h0));
    __nv_bfloat162 l1 = __floats2bfloat162_rn(v.z - __low2float(h1), v.w - __high2float(h1));
    *reinterpret_cast<__nv_bfloat162*>(h + i)     = h0;
    *reinterpret_cast<__nv_bfloat162*>(h + i + 2) = h1;
    *reinterpret_cast<__nv_bfloat162*>(l + i)     = l0;
    *reinterpret_cast<__nv_bfloat162*>(l + i + 2) = l1;
}

// weight [K][Ns] -> concatenated [K][PROJ_W] at column offset
__global__ void cvt_wcat(const float* __restrict__ s,
                         __nv_bfloat16* __restrict__ h, __nv_bfloat16* __restrict__ l,
                         int Ns, int off, int total)
{
    int i = (blockIdx.x * blockDim.x + threadIdx.x) * 4;
    if (i >= total) return;
    int k = i / Ns, n = i % Ns;
    size_t d = (size_t)k * PROJ_W + off + n;
    float4 v = *reinterpret_cast<const float4*>(s + i);
    __nv_bfloat162 h0 = __floats2bfloat162_rn(v.x, v.y);
    __nv_bfloat162 h1 = __floats2bfloat162_rn(v.z, v.w);
    __nv_bfloat162 l0 = __floats2bfloat162_rn(v.x - __low2float(h0), v.y - __high2float(h0));
    __nv_bfloat162 l1 = __floats2bfloat162_rn(v.z - __low2float(h1), v.w - __high2float(h1));
    *reinterpret_cast<__nv_bfloat162*>(h + d)     = h0;
    *reinterpret_cast<__nv_bfloat162*>(h + d + 2) = h1;
    *reinterpret_cast<__nv_bfloat162*>(l + d)     = l0;
    *reinterpret_cast<__nv_bfloat162*>(l + d + 2) = l1;
}

// ================= bf16x3 HMMA GEMM, cp.async pipelined =================
// Tile 128x128, BK=32, 256 threads, double-buffered, 2 CTAs/SM.
// Stage: Ahi[128x80B]=10240 | Alo=10240 | Bhi[32x288B]=9216 | Blo=9216
// B pitch 288B: row shift = 2 slots -> bank slot (2k + s^k) mod 8 is a
// permutation for every s  => conflict-free ldmatrix.trans.
#define HSTG 38912
#define HSM2 (2 * HSTG)

__device__ __forceinline__ void issue_stage(
    uint32_t st,
    const __nv_bfloat16* __restrict__ Ahi, const __nv_bfloat16* __restrict__ Alo,
    const __nv_bfloat16* __restrict__ Bhi, const __nv_bfloat16* __restrict__ Blo,
    int bm, int bn, int kt, int N, int K, int tid)
{
#pragma unroll
    for (int hq = 0; hq < 2; hq++) {
        int c = tid + hq * 256;
        int m = c >> 2, sl = c & 3;
        size_t so = (size_t)(bm + m) * K + kt + sl * 8;
        uint32_t d = st + m * 80 + sl * 16;
        cpa16(d,          Ahi + so);
        cpa16(d + 10240,  Alo + so);
    }
#pragma unroll
    for (int hq = 0; hq < 2; hq++) {
        int c = tid + hq * 256;
        int k = c >> 4, n8 = c & 15;
        size_t so = (size_t)(kt + k) * N + bn + n8 * 8;
        uint32_t sw = (uint32_t)(((n8 & 8) | ((n8 ^ k) & 7)) * 16);
        uint32_t d = st + 20480 + k * 288 + sw;
        cpa16(d,         Bhi + so);
        cpa16(d + 9216,  Blo + so);
    }
}

__global__ void __launch_bounds__(256, 2) hgemm2(
    const __nv_bfloat16* __restrict__ Ahi, const __nv_bfloat16* __restrict__ Alo,
    const __nv_bfloat16* __restrict__ Bhi, const __nv_bfloat16* __restrict__ Blo,
    float* __restrict__ C, int M, int N, int K)
{
    extern __shared__ char sm2[];
    const uint32_t sbase = smem_u32(sm2);
    const int tid = threadIdx.x, lane = tid & 31, w = tid >> 5;
    const int wm = (w >> 2) * 64, wn = (w & 3) * 32;
    const int bm = blockIdx.y * 128, bn = blockIdx.x * 128;
    const int wslot = (w & 3) * 4;

    float acc[4][4][4];
#pragma unroll
    for (int i = 0; i < 4; i++)
#pragma unroll
        for (int j = 0; j < 4; j++)
#pragma unroll
            for (int q = 0; q < 4; q++) acc[i][j][q] = 0.f;

    const int niter = K >> 5;
    const uint32_t a_lane = (uint32_t)((wm + (lane & 15)) * 80 + ((lane >> 4) << 4));

    issue_stage(sbase, Ahi, Alo, Bhi, Blo, bm, bn, 0, N, K, tid);
    asm volatile("cp.async.commit_group;" ::: "memory");

    for (int it = 0; it < niter; ++it) {
        if (it + 1 < niter) {
            issue_stage(sbase + (uint32_t)((it + 1) & 1) * HSTG,
                        Ahi, Alo, Bhi, Blo, bm, bn, (it + 1) << 5, N, K, tid);
            asm volatile("cp.async.commit_group;" ::: "memory");
            asm volatile("cp.async.wait_group 1;" ::: "memory");
        } else {
            asm volatile("cp.async.wait_group 0;" ::: "memory");
        }
        __syncthreads();

        const uint32_t sA   = sbase + (uint32_t)(it & 1) * HSTG;
        const uint32_t sAlo = sA + 10240;
        const uint32_t sB   = sA + 20480;
        const uint32_t sBlo = sB + 9216;

#pragma unroll
        for (int ks = 0; ks < 32; ks += 16) {
            const int klane = ks + (lane & 15);
            const uint32_t bro = (uint32_t)(klane * 288);
            uint32_t bh[4][2], bl[4][2];
#pragma unroll
            for (int ni = 0; ni < 4; ni++) {
                const int slot = wslot + ni;
                const uint32_t off = bro + (uint32_t)((((slot ^ klane) & 7) | (slot & 8)) * 16);
                ldmx2t(bh[ni], sB + off);
                ldmx2t(bl[ni], sBlo + off);
            }
            const uint32_t ao = a_lane + ks * 2;
#pragma unroll
            for (int mi = 0; mi < 4; mi++) {
                uint32_t ah[4], al_[4];
                ldmx4(ah,  sA   + ao + mi * (16 * 80));
                ldmx4(al_, sAlo + ao + mi * (16 * 80));
#pragma unroll
                for (int ni = 0; ni < 4; ni++) {
                    mma16816(acc[mi][ni], ah,  bh[ni]);
                    mma16816(acc[mi][ni], al_, bh[ni]);
                    mma16816(acc[mi][ni], ah,  bl[ni]);
                }
            }
        }
        __syncthreads();
    }

    // epilogue
#pragma unroll
    for (int mi = 0; mi < 4; mi++) {
        const int row = bm + wm + mi * 16 + (lane >> 2);
#pragma unroll
        for (int ni = 0; ni < 4; ni++) {
            const int col = bn + wn + ni * 8 + (lane & 3) * 2;
            float2 v0; v0.x = acc[mi][ni][0]; v0.y = acc[mi][ni][1];
            float2 v1; v1.x = acc[mi][ni][2]; v1.y = acc[mi][ni][3];
            *reinterpret_cast<float2*>(C + (size_t)row * N + col)       = v0;
            *reinterpret_cast<float2*>(C + (size_t)(row + 8) * N + col) = v1;
        }
    }
}

// ---------------- fused tiny projections (b0|b1|a) + activations ----------------
// one block per row; 18 outputs; reads x once.
__global__ __launch_bounds__(128) void gemm18(
    const float* __restrict__ A, const float* __restrict__ b_ws,
    const float* __restrict__ a_w, const float* __restrict__ A_log,
    const float* __restrict__ dtb,
    float* __restrict__ be0, float* __restrict__ be1, float* __restrict__ gd)
{
    __shared__ float red[128 * 20];
    const int r = blockIdx.x, tid = threadIdx.x;
    float acc[18];
#pragma unroll
    for (int j = 0; j < 18; j++) acc[j] = 0.f;
    const float* arow = A + (size_t)r * HID;
    const float* w0 = b_ws;
    const float* w1 = b_ws + (size_t)HID * 6;
    const float* w2 = a_w;
    for (int k = tid; k < HID; k += 128) {
        float a = arow[k];
#pragma unroll
        for (int j = 0; j < 6; j++) acc[j]      = fmaf(a, w0[k * 6 + j], acc[j]);
#pragma unroll
        for (int j = 0; j < 6; j++) acc[6 + j]  = fmaf(a, w1[k * 6 + j], acc[6 + j]);
#pragma unroll
        for (int j = 0; j < 6; j++) acc[12 + j] = fmaf(a, w2[k * 6 + j], acc[12 + j]);
    }
#pragma unroll
    for (int j = 0; j < 18; j++) red[tid * 20 + j] = acc[j];
    __syncthreads();
    for (int s = 64; s > 0; s >>= 1) {
        if (tid < s) {
#pragma unroll
            for (int j = 0; j < 18; j++) red[tid * 20 + j] += red[(tid + s) * 20 + j];
        }
        __syncthreads();
    }
    if (tid < 18) {
        float v = red[tid];
        int j = tid % 6;
        if (tid < 6) {
            be0[r * 6 + tid] = 1.f / (1.f + expf(-v));
        } else if (tid < 12) {
            be1[r * 6 + j] = 1.f / (1.f + expf(-v));
        } else {
            float z = v + dtb[j];
            float sp = (z > 20.f) ? z : log1pf(expf(z));
            gd[r * 6 + j] = -expf(A_log[j]) * sp;
        }
    }
}

// ---------------- conv(4) + SiLU + per-head L2 norm (q/k path) ----------------
__global__ __launch_bounds__(256) void conv_silu_norm(
    const float* __restrict__ Z, int zoff, const float* __restrict__ W,
    float* __restrict__ Out, float outscale)
{
    const int r = blockIdx.x, h = blockIdx.y, tid = threadIdx.x;
    const int b = r >> 10, t = r & 1023;
    const int c = h * DK + tid;
    float acc = 0.f;
#pragma unroll
    for (int j = 0; j < 4; j++) {
        int tj = t - 3 + j;
        if (tj >= 0) acc = fmaf(Z[(size_t)(b * TLEN + tj) * PROJ_W + zoff + c], W[c * 4 + j], acc);
    }
    float y = acc / (1.f + expf(-acc));   // silu
    __shared__ float sred[256];
    sred[tid] = y * y;
    __syncthreads();
    for (int s = 128; s > 0; s >>= 1) {
        if (tid < s) sred[tid] += sred[tid + s];
        __syncthreads();
    }
    float scale = rsqrtf(sred[0] + 1e-12f) * outscale;
    Out[(size_t)r * KEY_DIM + c] = y * scale;
}

// ---------------- conv(4) + SiLU for v path ----------------
__global__ void conv_silu_v(
    const float* __restrict__ Z, int zoff, const float* __restrict__ W,
    float* __restrict__ Out)
{
    int idx = blockIdx.x * blockDim.x + threadIdx.x;
    if (idx >= RROWS * VAL_DIM) return;
    int c = idx % VAL_DIM;
    int r = idx / VAL_DIM;
    int b = r >> 10, t = r & 1023;
    float acc = 0.f;
#pragma unroll
    for (int j = 0; j < 4; j++) {
        int tj = t - 3 + j;
        if (tj >= 0) acc = fmaf(Z[(size_t)(b * TLEN + tj) * PROJ_W + zoff + c], W[c * 4 + j], acc);
    }
    Out[idx] = acc / (1.f + expf(-acc));
}

// ---------------- packed f32x2 helpers ----------------
union F2U { float2 f; unsigned long long u; };

__device__ __forceinline__ F2U ffma2(F2U a, F2U b, F2U c) {
    F2U r;
    asm("fma.rn.f32x2 %0, %1, %2, %3;" : "=l"(r.u) : "l"(a.u), "l"(b.u), "l"(c.u));
    return r;
}
__device__ __forceinline__ F2U fmul2(F2U a, F2U b) {
    F2U r;
    asm("mul.rn.f32x2 %0, %1, %2;" : "=l"(r.u) : "l"(a.u), "l"(b.u));
    return r;
}

// ---------------- gated delta-rule recurrence v2 ----------------
// 128 threads = 4 warps; each half-warp owns TWO adjacent DV-columns
// (k/q LDS amortized across both). State in registers (S0/S1: 8 F2U each).
// Triple-buffered smem staging of k0/k1/q with ONE __syncthreads per step;
// all global loads prefetched one step ahead.
// grid (BSZ*HH = 12, DV/16 = 32).
__global__ void __launch_bounds__(128, 3) delta_recur2(
    const float* __restrict__ Qn,  const float* __restrict__ Kn0, const float* __restrict__ Kn1,
    const float* __restrict__ Vs0, const float* __restrict__ Vs1,
    const float* __restrict__ Be0, const float* __restrict__ Be1,
    const float* __restrict__ Gd,  float* __restrict__ O)
{
    const int bh = blockIdx.x;
    const int b = bh / HH, h = bh % HH;
    const int tid = threadIdx.x;
    const int w = tid >> 5, lane = tid & 31;
    const int half = lane >> 4, l0 = lane & 15;
    const int col0 = blockIdx.y * 16 + w * 4 + half * 2;

    __shared__ __align__(16) float sk[3][3][256];   // [buf][k0,k1,q][dim]

    F2U S0[8], S1[8];
#pragma unroll
    for (int j = 0; j < 8; j++) { S0[j].u = 0ull; S1[j].u = 0ull; }

    // ---- stage t=0 + load t=0 scalars/v ----
    {
        const size_t kb = (size_t)(b * TLEN) * KEY_DIM + h * DK + tid * 2;
        *reinterpret_cast<float2*>(&sk[0][0][tid * 2]) = *reinterpret_cast<const float2*>(Kn0 + kb);
        *reinterpret_cast<float2*>(&sk[0][1][tid * 2]) = *reinterpret_cast<const float2*>(Kn1 + kb);
        *reinterpret_cast<float2*>(&sk[0][2][tid * 2]) = *reinterpret_cast<const float2*>(Qn + kb);
    }
    const size_t vb0 = (size_t)(b * TLEN) * VAL_DIM + h * DV + col0;
    float2 vc0 = *reinterpret_cast<const float2*>(Vs0 + vb0);
    float2 vc1 = *reinterpret_cast<const float2*>(Vs1 + vb0);
    const int gi0 = (b * TLEN) * HH + h;
    float gcur = Gd[gi0], b0cur = Be0[gi0], b1cur = Be1[gi0];
    __syncthreads();

    int cur = 0;
    for (int t = 0; t < TLEN; t++) {
        const int nxt = (cur == 2) ? 0 : cur + 1;
        const int r = b * TLEN + t;
        const bool more = (t + 1 < TLEN);

        // prefetch t+1
        float2 kr0, kr1, krq, vn0, vn1;
        float gn = 0.f, bn0 = 0.f, bn1 = 0.f;
        if (more) {
            const size_t kb = (size_t)(r + 1) * KEY_DIM + h * DK + tid * 2;
            kr0 = *reinterpret_cast<const float2*>(Kn0 + kb);
            kr1 = *reinterpret_cast<const float2*>(Kn1 + kb);
            krq = *reinterpret_cast<const float2*>(Qn + kb);
            const size_t vb = (size_t)(r + 1) * VAL_DIM + h * DV + col0;
            vn0 = *reinterpret_cast<const float2*>(Vs0 + vb);
            vn1 = *reinterpret_cast<const float2*>(Vs1 + vb);
            const int gi = (r + 1) * HH + h;
            gn = Gd[gi]; bn0 = Be0[gi]; bn1 = Be1[gi];
        }

        const float decay = expf(gcur);
        const float2* pk0 = reinterpret_cast<const float2*>(sk[cur][0]);
        const float2* pk1 = reinterpret_cast<const float2*>(sk[cur][1]);
        const float2* pq  = reinterpret_cast<const float2*>(sk[cur][2]);

        F2U rk[8];
        // ---- pass 0: k0 ----
#pragma unroll
        for (int j = 0; j < 8; j++) rk[j].f = pk0[j * 16 + l0];
        F2U aA, aB; aA.u = 0ull; aB.u = 0ull;
#pragma unroll
        for (int j = 0; j < 8; j++) { aA = ffma2(rk[j], S0[j], aA); aB = ffma2(rk[j], S1[j], aB); }
        float dA = aA.f.x + aA.f.y, dB = aB.f.x + aB.f.y;
#pragma unroll
        for (int m = 8; m > 0; m >>= 1) {
            dA += __shfl_xor_sync(0xffffffffu, dA, m);
            dB += __shfl_xor_sync(0xffffffffu, dB, m);
        }
        dA *= decay; dB *= decay;
        const float u0A = (vc0.x - dA) * b0cur, u0B = (vc0.y - dB) * b0cur;
        F2U dec2; dec2.f = make_float2(decay, decay);
        F2U uA; uA.f = make_float2(u0A, u0A);
        F2U uB; uB.f = make_float2(u0B, u0B);
#pragma unroll
        for (int j = 0; j < 8; j++) {
            S0[j] = ffma2(S0[j], dec2, fmul2(rk[j], uA));
            S1[j] = ffma2(S1[j], dec2, fmul2(rk[j], uB));
        }
        // ---- pass 1: k1 ----
#pragma unroll
        for (int j = 0; j < 8; j++) rk[j].f = pk1[j * 16 + l0];
        aA.u = 0ull; aB.u = 0ull;
#pragma unroll
        for (int j = 0; j < 8; j++) { aA = ffma2(rk[j], S0[j], aA); aB = ffma2(rk[j], S1[j], aB); }
        dA = aA.f.x + aA.f.y; dB = aB.f.x + aB.f.y;
#pragma unroll
        for (int m = 8; m > 0; m >>= 1) {
            dA += __shfl_xor_sync(0xffffffffu, dA, m);
            dB += __shfl_xor_sync(0xffffffffu, dB, m);
        }
        const float u1A = (vc1.x - dA) * b1cur, u1B = (vc1.y - dB) * b1cur;
        uA.f = make_float2(u1A, u1A); uB.f = make_float2(u1B, u1B);
#pragma unroll
        for (int j = 0; j < 8; j++) {
            S0[j] = ffma2(rk[j], uA, S0[j]);
            S1[j] = ffma2(rk[j], uB, S1[j]);
        }
        // ---- readout: q ----
#pragma unroll
        for (int j = 0; j < 8; j++) rk[j].f = pq[j * 16 + l0];
        aA.u = 0ull; aB.u = 0ull;
#pragma unroll
        for (int j = 0; j < 8; j++) { aA = ffma2(rk[j], S0[j], aA); aB = ffma2(rk[j], S1[j], aB); }
        dA = aA.f.x + aA.f.y; dB = aB.f.x + aB.f.y;
#pragma unroll
        for (int m = 8; m > 0; m >>= 1) {
            dA += __shfl_xor_sync(0xffffffffu, dA, m);
            dB += __shfl_xor_sync(0xffffffffu, dB, m);
        }
        if (l0 == 0) {
            float2 ov; ov.x = dA; ov.y = dB;
            *reinterpret_cast<float2*>(O + (size_t)(r * HH + h) * DV + col0) = ov;
        }

        // ---- stage t+1 ----
        if (more) {
            *reinterpret_cast<float2*>(&sk[nxt][0][tid * 2]) = kr0;
            *reinterpret_cast<float2*>(&sk[nxt][1][tid * 2]) = kr1;
            *reinterpret_cast<float2*>(&sk[nxt][2][tid * 2]) = krq;
            vc0 = vn0; vc1 = vn1; gcur = gn; b0cur = bn0; b1cur = bn1;
            __syncthreads();
        }
        cur = nxt;
    }
}

// ---------------- RMS norm over DV + gated SiLU -> bf16 hi/lo ----------------
__global__ __launch_bounds__(256) void rms_gate(
    const float* __restrict__ Ob, const float* __restrict__ Gx,
    const float* __restrict__ onw,
    __nv_bfloat16* __restrict__ Yh, __nv_bfloat16* __restrict__ Yl)
{
    const int r = blockIdx.x, h = blockIdx.y, tid = threadIdx.x;
    const size_t base = (size_t)(r * HH + h) * DV;
    const size_t gbase = (size_t)r * PROJ_W + OFF_G + h * DV;
    float o0 = Ob[base + tid], o1 = Ob[base + tid + 256];
    __shared__ float sred[256];
    sred[tid] = o0 * o0 + o1 * o1;
    __syncthreads();
    for (int s = 128; s > 0; s >>= 1) {
        if (tid < s) sred[tid] += sred[tid + s];
        __syncthreads();
    }
    float scale = rsqrtf(sred[0] * (1.f / 512.f) + 1e-5f);
    float g0 = Gx[gbase + tid], g1 = Gx[gbase + tid + 256];
    float y0 = o0 * scale * onw[tid]       * (g0 / (1.f + expf(-g0)));
    float y1 = o1 * scale * onw[tid + 256] * (g1 / (1.f + expf(-g1)));
    __nv_bfloat16 h0 = __float2bfloat16_rn(y0);
    __nv_bfloat16 h1 = __float2bfloat16_rn(y1);
    Yh[base + tid]       = h0;
    Yh[base + tid + 256] = h1;
    Yl[base + tid]       = __float2bfloat16_rn(y0 - __bfloat162float(h0));
    Yl[base + tid + 256] = __float2bfloat16_rn(y1 - __bfloat162float(h1));
}

// ---------------- launch ----------------
extern "C" void kernel_launch(void* const* d_in, const int* in_sizes, int n_in,
                              void* d_out, int out_size)
{
    const float* x     = (const float*)d_in[0];
    const float* q_w   = (const float*)d_in[1];
    const float* k_ws  = (const float*)d_in[2];
    const float* v_ws  = (const float*)d_in[3];
    const float* b_ws  = (const float*)d_in[4];
    const float* a_w   = (const float*)d_in[5];
    const float* g_w   = (const float*)d_in[6];
    const float* o_w   = (const float*)d_in[7];
    const float* qcw   = (const float*)d_in[8];
    const float* kcw   = (const float*)d_in[9];
    const float* vcw   = (const float*)d_in[10];
    const float* A_log = (const float*)d_in[11];
    const float* dtb   = (const float*)d_in[12];
    const float* onw   = (const float*)d_in[13];
    float* out = (float*)d_out;

    float *proj, *qn, *kn0, *kn1, *vs0, *vs1, *ob;
    float *be0, *be1, *gd;
    __nv_bfloat16 *xhi, *xlo, *wch, *wcl, *owh, *owl, *ybh, *ybl;
    cudaGetSymbolAddress((void**)&proj, g_proj);
    cudaGetSymbolAddress((void**)&xhi, g_xhi);
    cudaGetSymbolAddress((void**)&xlo, g_xlo);
    cudaGetSymbolAddress((void**)&wch, g_wch);
    cudaGetSymbolAddress((void**)&wcl, g_wcl);
    cudaGetSymbolAddress((void**)&owh, g_owh);
    cudaGetSymbolAddress((void**)&owl, g_owl);
    cudaGetSymbolAddress((void**)&ybh, g_ybh);
    cudaGetSymbolAddress((void**)&ybl, g_ybl);
    cudaGetSymbolAddress((void**)&qn,  g_qn);
    cudaGetSymbolAddress((void**)&kn0, g_kn0);
    cudaGetSymbolAddress((void**)&kn1, g_kn1);
    cudaGetSymbolAddress((void**)&vs0, g_vs0);
    cudaGetSymbolAddress((void**)&vs1, g_vs1);
    cudaGetSymbolAddress((void**)&ob,  g_ob);
    cudaGetSymbolAddress((void**)&be0, g_be0);
    cudaGetSymbolAddress((void**)&be1, g_be1);
    cudaGetSymbolAddress((void**)&gd,  g_gd);

    cudaFuncSetAttribute(hgemm2, cudaFuncAttributeMaxDynamicSharedMemorySize, HSM2);

    // 0) fp32 -> bf16 hi/lo splits
    {
        int n = RROWS * HID;
        cvt_split<<<(n/4 + 255)/256, 256>>>(x, xhi, xlo, n);
    }
    {
        int t;
        t = HID * KEY_DIM;
        cvt_wcat<<<(t/4 + 255)/256, 256>>>(q_w,                          wch, wcl, KEY_DIM, OFF_Q,  t);
        cvt_wcat<<<(t/4 + 255)/256, 256>>>(k_ws,                         wch, wcl, KEY_DIM, OFF_K0, t);
        cvt_wcat<<<(t/4 + 255)/256, 256>>>(k_ws + (size_t)HID*KEY_DIM,   wch, wcl, KEY_DIM, OFF_K1, t);
        t = HID * VAL_DIM;
        cvt_wcat<<<(t/4 + 255)/256, 256>>>(v_ws,                         wch, wcl, VAL_DIM, OFF_V0, t);
        cvt_wcat<<<(t/4 + 255)/256, 256>>>(v_ws + (size_t)HID*VAL_DIM,   wch, wcl, VAL_DIM, OFF_V1, t);
        cvt_wcat<<<(t/4 + 255)/256, 256>>>(g_w,                          wch, wcl, VAL_DIM, OFF_G,  t);
    }
    {
        int n = VAL_DIM * HID;
        cvt_split<<<(n/4 + 255)/256, 256>>>(o_w, owh, owl, n);
    }

    // 1) merged projection GEMM + fused tiny projections/activations
    hgemm2<<<dim3(PROJ_W/128, RROWS/128), 256, HSM2>>>(xhi, xlo, wch, wcl, proj, RROWS, PROJ_W, HID);
    gemm18<<<RROWS, 128>>>(x, b_ws, a_w, A_log, dtb, be0, be1, gd);

    // 2) conv / norms
    conv_silu_norm<<<dim3(RROWS, HH), 256>>>(proj, OFF_Q,  qcw, qn, 0.0625f);  // * DK^-0.5
    conv_silu_norm<<<dim3(RROWS, HH), 256>>>(proj, OFF_K0, kcw, kn0, 1.f);
    conv_silu_norm<<<dim3(RROWS, HH), 256>>>(proj, OFF_K1, kcw + KEY_DIM * 4, kn1, 1.f);
    conv_silu_v<<<(RROWS * VAL_DIM + 255) / 256, 256>>>(proj, OFF_V0, vcw, vs0);
    conv_silu_v<<<(RROWS * VAL_DIM + 255) / 256, 256>>>(proj, OFF_V1, vcw + VAL_DIM * 4, vs1);

    // 3) sequential gated delta rule
    delta_recur2<<<dim3(BSZ * HH, DV / 16), 128>>>(qn, kn0, kn1, vs0, vs1, be0, be1, gd, ob);

    // 4) output norm + gate (emits bf16 hi/lo) + final projection
    rms_gate<<<dim3(RROWS, HH), 256>>>(ob, proj, onw, ybh, ybl);
    hgemm2<<<dim3(HID/128, RROWS/128), 256, HSM2>>>(ybh, ybl, owh, owl, out, RROWS, HID, VAL_DIM);
}

// round 11
// speedup vs baseline: 2.4654x; 1.0606x over previous
#include <cuda_runtime.h>
#include <cuda_bf16.h>
#include <cstdint>

// ---------------- problem constants ----------------
#define BSZ 2
#define TLEN 1024
#define HID 2048
#define NHEADS 2
#define HH 6
#define DK 256
#define DV 512
#define KEY_DIM 1536   // HH*DK
#define VAL_DIM 3072   // HH*DV
#define RROWS 2048     // BSZ*TLEN

// concatenated projection layout: [ q | k0 | k1 | v0 | v1 | gate ]
#define PROJ_W 13824
#define OFF_Q  0
#define OFF_K0 1536
#define OFF_K1 3072
#define OFF_V0 4608
#define OFF_V1 7680
#define OFF_G  10752

// ---------------- scratch (static device memory; no allocs) ----------------
__device__ float g_proj[(size_t)RROWS * PROJ_W];
__device__ __nv_bfloat16 g_xhi[(size_t)RROWS * HID];
__device__ __nv_bfloat16 g_xlo[(size_t)RROWS * HID];
__device__ __nv_bfloat16 g_wch[(size_t)HID * PROJ_W];
__device__ __nv_bfloat16 g_wcl[(size_t)HID * PROJ_W];
__device__ __nv_bfloat16 g_owh[(size_t)VAL_DIM * HID];
__device__ __nv_bfloat16 g_owl[(size_t)VAL_DIM * HID];
__device__ __nv_bfloat16 g_ybh[(size_t)RROWS * VAL_DIM];
__device__ __nv_bfloat16 g_ybl[(size_t)RROWS * VAL_DIM];
__device__ float g_qn [RROWS*KEY_DIM];
__device__ float g_kn0[RROWS*KEY_DIM];
__device__ float g_kn1[RROWS*KEY_DIM];
__device__ float g_vs0[RROWS*VAL_DIM];
__device__ float g_vs1[RROWS*VAL_DIM];
__device__ float g_ob [RROWS*VAL_DIM];
__device__ float g_be0[RROWS*HH];
__device__ float g_be1[RROWS*HH];
__device__ float g_gd [RROWS*HH];

// ================= helpers =================
__device__ __forceinline__ uint32_t smem_u32(const void* p) {
    uint32_t a;
    asm("{ .reg .u64 t; cvta.to.shared.u64 t, %1; cvt.u32.u64 %0, t; }" : "=r"(a) : "l"(p));
    return a;
}
__device__ __forceinline__ void ldmx4(uint32_t* r, uint32_t addr) {
    asm volatile("ldmatrix.sync.aligned.m8n8.x4.shared.b16 {%0,%1,%2,%3}, [%4];"
        : "=r"(r[0]), "=r"(r[1]), "=r"(r[2]), "=r"(r[3]) : "r"(addr));
}
__device__ __forceinline__ void ldmx2t(uint32_t* r, uint32_t addr) {
    asm volatile("ldmatrix.sync.aligned.m8n8.x2.trans.shared.b16 {%0,%1}, [%2];"
        : "=r"(r[0]), "=r"(r[1]) : "r"(addr));
}
__device__ __forceinline__ void mma16816(float* c, const uint32_t* a, const uint32_t* b) {
    asm volatile(
        "mma.sync.aligned.m16n8k16.row.col.f32.bf16.bf16.f32 "
        "{%0,%1,%2,%3}, {%4,%5,%6,%7}, {%8,%9}, {%0,%1,%2,%3};"
        : "+f"(c[0]), "+f"(c[1]), "+f"(c[2]), "+f"(c[3])
        : "r"(a[0]), "r"(a[1]), "r"(a[2]), "r"(a[3]), "r"(b[0]), "r"(b[1]));
}
__device__ __forceinline__ void cpa16(uint32_t dst, const void* src) {
    asm volatile("cp.async.cg.shared.global [%0], [%1], 16;" :: "r"(dst), "l"(src));
}

__device__ __forceinline__ void split_write(
    float4 v, __nv_bfloat16* __restrict__ h, __nv_bfloat16* __restrict__ l, size_t d)
{
    __nv_bfloat162 h0 = __floats2bfloat162_rn(v.x, v.y);
    __nv_bfloat162 h1 = __floats2bfloat162_rn(v.z, v.w);
    __nv_bfloat162 l0 = __floats2bfloat162_rn(v.x - __low2float(h0), v.y - __high2float(h0));
    __nv_bfloat162 l1 = __floats2bfloat162_rn(v.z - __low2float(h1), v.w - __high2float(h1));
    *reinterpret_cast<__nv_bfloat162*>(h + d)     = h0;
    *reinterpret_cast<__nv_bfloat162*>(h + d + 2) = h1;
    *reinterpret_cast<__nv_bfloat162*>(l + d)     = l0;
    *reinterpret_cast<__nv_bfloat162*>(l + d + 2) = l1;
}

// ================= fp32 -> bf16 hi/lo split (plain) =================
__global__ void cvt_split(const float* __restrict__ s,
                          __nv_bfloat16* __restrict__ h, __nv_bfloat16* __restrict__ l, int n)
{
    int i = (blockIdx.x * blockDim.x + threadIdx.x) * 4;
    if (i >= n) return;
    split_write(*reinterpret_cast<const float4*>(s + i), h, l, i);
}

// ================= ALL weight conversions in ONE launch =================
// segments (quads of 4 fp32):
//  [0, 786432)           q_w   -> wc @ OFF_Q   (Ns=1536)
//  [786432, 1572864)     k_ws0 -> wc @ OFF_K0
//  [1572864, 2359296)    k_ws1 -> wc @ OFF_K1
//  [2359296, 3932160)    v_ws0 -> wc @ OFF_V0  (Ns=3072)
//  [3932160, 5505024)    v_ws1 -> wc @ OFF_V1
//  [5505024, 7077888)    g_w   -> wc @ OFF_G
//  [7077888, 8650752)    o_w   -> owh/owl plain
#define CVTW_BLOCKS 33792
__global__ void cvt_w_all(
    const float* __restrict__ q_w, const float* __restrict__ k_ws,
    const float* __restrict__ v_ws, const float* __restrict__ g_w,
    const float* __restrict__ o_w,
    __nv_bfloat16* __restrict__ wch, __nv_bfloat16* __restrict__ wcl,
    __nv_bfloat16* __restrict__ owh, __nv_bfloat16* __restrict__ owl)
{
    int qd = blockIdx.x * blockDim.x + threadIdx.x;   // quad index
    const float* s;
    int Ns, off;
    if (qd < 2359296) {
        int seg = qd / 786432;
        qd -= seg * 786432;
        s = (seg == 0) ? q_w : k_ws + (size_t)(seg - 1) * ((size_t)HID * KEY_DIM);
        Ns = KEY_DIM; off = seg * KEY_DIM;
    } else if (qd < 7077888) {
        int qq = qd - 2359296;
        int seg = qq / 1572864;
        qd = qq - seg * 1572864;
        s = (seg == 2) ? g_w : v_ws + (size_t)seg * ((size_t)HID * VAL_DIM);
        Ns = VAL_DIM; off = OFF_V0 + seg * VAL_DIM;
    } else {
        int i = (qd - 7077888) * 4;
        split_write(*reinterpret_cast<const float4*>(o_w + i), owh, owl, (size_t)i);
        return;
    }
    int i = qd * 4;
    int k = i / Ns, n = i - k * Ns;
    size_t d = (size_t)k * PROJ_W + off + n;
    split_write(*reinterpret_cast<const float4*>(s + i), wch, wcl, d);
}

// ================= bf16x3 HMMA GEMM, 3-stage cp.async =================
// Tile 128x128, BK=32, 256 threads, 2 CTAs/SM, 3-stage pipeline.
// Stage: Ahi[128x80B]=10240 | Alo=10240 | Bhi[32x256B]=8192 | Blo=8192 = 36864
// A pitch 80B: 16B slot (5m+c) mod 8 -> conflict-free ldmatrix.
// B pitch 256B + XOR swizzle slot=(n8&8)|((n8^k)&7) -> conflict-free ldmatrix.trans.
#define HSTG 36864
#define HSM3 (3 * HSTG)

__device__ __forceinline__ void issue_stage(
    uint32_t st,
    const __nv_bfloat16* __restrict__ Ahi, const __nv_bfloat16* __restrict__ Alo,
    const __nv_bfloat16* __restrict__ Bhi, const __nv_bfloat16* __restrict__ Blo,
    int bm, int bn, int kt, int N, int K, int tid)
{
#pragma unroll
    for (int hq = 0; hq < 2; hq++) {
        int c = tid + hq * 256;
        int m = c >> 2, sl = c & 3;
        size_t so = (size_t)(bm + m) * K + kt + sl * 8;
        uint32_t d = st + m * 80 + sl * 16;
        cpa16(d,          Ahi + so);
        cpa16(d + 10240,  Alo + so);
    }
#pragma unroll
    for (int hq = 0; hq < 2; hq++) {
        int c = tid + hq * 256;
        int k = c >> 4, n8 = c & 15;
        size_t so = (size_t)(kt + k) * N + bn + n8 * 8;
        uint32_t sw = (uint32_t)(((n8 & 8) | ((n8 ^ k) & 7)) * 16);
        uint32_t d = st + 20480 + k * 256 + sw;
        cpa16(d,         Bhi + so);
        cpa16(d + 8192,  Blo + so);
    }
}

__global__ void __launch_bounds__(256, 2) hgemm2(
    const __nv_bfloat16* __restrict__ Ahi, const __nv_bfloat16* __restrict__ Alo,
    const __nv_bfloat16* __restrict__ Bhi, const __nv_bfloat16* __restrict__ Blo,
    float* __restrict__ C, int M, int N, int K)
{
    extern __shared__ char sm2[];
    const uint32_t sbase = smem_u32(sm2);
    const int tid = threadIdx.x, lane = tid & 31, w = tid >> 5;
    const int wm = (w >> 2) * 64, wn = (w & 3) * 32;
    const int bm = blockIdx.y * 128, bn = blockIdx.x * 128;
    const int wslot = (w & 3) * 4;

    float acc[4][4][4];
#pragma unroll
    for (int i = 0; i < 4; i++)
#pragma unroll
        for (int j = 0; j < 4; j++)
#pragma unroll
            for (int q = 0; q < 4; q++) acc[i][j][q] = 0.f;

    const int niter = K >> 5;
    const uint32_t a_lane = (uint32_t)((wm + (lane & 15)) * 80 + ((lane >> 4) << 4));

    // prologue: 2 stages in flight
    issue_stage(sbase,        Ahi, Alo, Bhi, Blo, bm, bn, 0,  N, K, tid);
    asm volatile("cp.async.commit_group;" ::: "memory");
    issue_stage(sbase + HSTG, Ahi, Alo, Bhi, Blo, bm, bn, 32, N, K, tid);
    asm volatile("cp.async.commit_group;" ::: "memory");

    int cbuf = 0;   // compute buffer
    int ibuf = 2;   // next issue buffer
    for (int it = 0; it < niter; ++it) {
        if (it + 2 < niter) {
            issue_stage(sbase + (uint32_t)ibuf * HSTG,
                        Ahi, Alo, Bhi, Blo, bm, bn, (it + 2) << 5, N, K, tid);
            asm volatile("cp.async.commit_group;" ::: "memory");
            asm volatile("cp.async.wait_group 2;" ::: "memory");
            if (++ibuf == 3) ibuf = 0;
        } else if (it + 1 < niter) {
            asm volatile("cp.async.wait_group 1;" ::: "memory");
        } else {
            asm volatile("cp.async.wait_group 0;" ::: "memory");
        }
        __syncthreads();

        const uint32_t sA   = sbase + (uint32_t)cbuf * HSTG;
        const uint32_t sAlo = sA + 10240;
        const uint32_t sB   = sA + 20480;
        const uint32_t sBlo = sB + 8192;

#pragma unroll
        for (int ks = 0; ks < 32; ks += 16) {
            const int klane = ks + (lane & 15);
            const uint32_t bro = (uint32_t)(klane * 256);
            uint32_t bh[4][2], bl[4][2];
#pragma unroll
            for (int ni = 0; ni < 4; ni++) {
                const int slot = wslot + ni;
                const uint32_t off = bro + (uint32_t)((((slot ^ klane) & 7) | (slot & 8)) * 16);
                ldmx2t(bh[ni], sB + off);
                ldmx2t(bl[ni], sBlo + off);
            }
            const uint32_t ao = a_lane + ks * 2;
#pragma unroll
            for (int mi = 0; mi < 4; mi++) {
                uint32_t ah[4], al_[4];
                ldmx4(ah,  sA   + ao + mi * (16 * 80));
                ldmx4(al_, sAlo + ao + mi * (16 * 80));
#pragma unroll
                for (int ni = 0; ni < 4; ni++) {
                    mma16816(acc[mi][ni], ah,  bh[ni]);
                    mma16816(acc[mi][ni], al_, bh[ni]);
                    mma16816(acc[mi][ni], ah,  bl[ni]);
                }
            }
        }
        __syncthreads();
        if (++cbuf == 3) cbuf = 0;
    }

    // epilogue
#pragma unroll
    for (int mi = 0; mi < 4; mi++) {
        const int row = bm + wm + mi * 16 + (lane >> 2);
#pragma unroll
        for (int ni = 0; ni < 4; ni++) {
            const int col = bn + wn + ni * 8 + (lane & 3) * 2;
            float2 v0; v0.x = acc[mi][ni][0]; v0.y = acc[mi][ni][1];
            float2 v1; v1.x = acc[mi][ni][2]; v1.y = acc[mi][ni][3];
            *reinterpret_cast<float2*>(C + (size_t)row * N + col)       = v0;
            *reinterpret_cast<float2*>(C + (size_t)(row + 8) * N + col) = v1;
        }
    }
}

// ---------------- fused tiny projections (b0|b1|a) + activations ----------------
__global__ __launch_bounds__(128) void gemm18(
    const float* __restrict__ A, const float* __restrict__ b_ws,
    const float* __restrict__ a_w, const float* __restrict__ A_log,
    const float* __restrict__ dtb,
    float* __restrict__ be0, float* __restrict__ be1, float* __restrict__ gd)
{
    __shared__ float red[128 * 20];
    const int r = blockIdx.x, tid = threadIdx.x;
    float acc[18];
#pragma unroll
    for (int j = 0; j < 18; j++) acc[j] = 0.f;
    const float* arow = A + (size_t)r * HID;
    const float* w0 = b_ws;
    const float* w1 = b_ws + (size_t)HID * 6;
    const float* w2 = a_w;
    for (int k = tid; k < HID; k += 128) {
        float a = arow[k];
#pragma unroll
        for (int j = 0; j < 6; j++) acc[j]      = fmaf(a, w0[k * 6 + j], acc[j]);
#pragma unroll
        for (int j = 0; j < 6; j++) acc[6 + j]  = fmaf(a, w1[k * 6 + j], acc[6 + j]);
#pragma unroll
        for (int j = 0; j < 6; j++) acc[12 + j] = fmaf(a, w2[k * 6 + j], acc[12 + j]);
    }
#pragma unroll
    for (int j = 0; j < 18; j++) red[tid * 20 + j] = acc[j];
    __syncthreads();
    for (int s = 64; s > 0; s >>= 1) {
        if (tid < s) {
#pragma unroll
            for (int j = 0; j < 18; j++) red[tid * 20 + j] += red[(tid + s) * 20 + j];
        }
        __syncthreads();
    }
    if (tid < 18) {
        float v = red[tid];
        int j = tid % 6;
        if (tid < 6) {
            be0[r * 6 + tid] = 1.f / (1.f + expf(-v));
        } else if (tid < 12) {
            be1[r * 6 + j] = 1.f / (1.f + expf(-v));
        } else {
            float z = v + dtb[j];
            float sp = (z > 20.f) ? z : log1pf(expf(z));
            gd[r * 6 + j] = -expf(A_log[j]) * sp;
        }
    }
}

// ================= ALL convolutions in ONE launch =================
// blocks [0, 36864): conv+silu+l2norm for q/k0/k1 (one block per (row, tensor*6+h))
// blocks [36864, 86016): elementwise conv+silu for v0/v1
#define CONV_QK_BLOCKS (RROWS * 18)
#define CONV_V_BLOCKS  ((RROWS * VAL_DIM * 2) / 256)
__global__ __launch_bounds__(256) void conv_all(
    const float* __restrict__ Z, const float* __restrict__ qcw,
    const float* __restrict__ kcw, const float* __restrict__ vcw,
    float* __restrict__ qn, float* __restrict__ kn0, float* __restrict__ kn1,
    float* __restrict__ vs0, float* __restrict__ vs1)
{
    const int bid = blockIdx.x, tid = threadIdx.x;
    if (bid < CONV_QK_BLOCKS) {
        const int r = bid / 18, u = bid - (bid / 18) * 18;
        const int tsel = u / 6, h = u - tsel * 6;
        const int zoff = tsel * KEY_DIM;
        const float* W = (tsel == 0) ? qcw : kcw + (size_t)(tsel - 1) * (KEY_DIM * 4);
        const float outscale = (tsel == 0) ? 0.0625f : 1.f;   // q: * DK^-0.5
        float* Out = (tsel == 0) ? qn : ((tsel == 1) ? kn0 : kn1);

        const int b = r >> 10, t = r & 1023;
        const int c = h * DK + tid;
        float acc = 0.f;
#pragma unroll
        for (int j = 0; j < 4; j++) {
            int tj = t - 3 + j;
            if (tj >= 0) acc = fmaf(Z[(size_t)(b * TLEN + tj) * PROJ_W + zoff + c], W[c * 4 + j], acc);
        }
        float y = acc / (1.f + expf(-acc));   // silu
        __shared__ float sred[256];
        sred[tid] = y * y;
        __syncthreads();
        for (int s = 128; s > 0; s >>= 1) {
            if (tid < s) sred[tid] += sred[tid + s];
            __syncthreads();
        }
        float scale = rsqrtf(sred[0] + 1e-12f) * outscale;
        Out[(size_t)r * KEY_DIM + c] = y * scale;
    } else {
        int idx = (bid - CONV_QK_BLOCKS) * 256 + tid;
        const int vsel = (idx >= RROWS * VAL_DIM) ? 1 : 0;
        idx -= vsel * (RROWS * VAL_DIM);
        const int zoff = OFF_V0 + vsel * VAL_DIM;
        const float* W = vcw + (size_t)vsel * (VAL_DIM * 4);
        float* Out = vsel ? vs1 : vs0;

        const int c = idx % VAL_DIM;
        const int r = idx / VAL_DIM;
        const int b = r >> 10, t = r & 1023;
        float acc = 0.f;
#pragma unroll
        for (int j = 0; j < 4; j++) {
            int tj = t - 3 + j;
            if (tj >= 0) acc = fmaf(Z[(size_t)(b * TLEN + tj) * PROJ_W + zoff + c], W[c * 4 + j], acc);
        }
        Out[idx] = acc / (1.f + expf(-acc));
    }
}

// ---------------- packed f32x2 helpers ----------------
union F2U { float2 f; unsigned long long u; };

__device__ __forceinline__ F2U ffma2(F2U a, F2U b, F2U c) {
    F2U r;
    asm("fma.rn.f32x2 %0, %1, %2, %3;" : "=l"(r.u) : "l"(a.u), "l"(b.u), "l"(c.u));
    return r;
}
__device__ __forceinline__ F2U fmul2(F2U a, F2U b) {
    F2U r;
    asm("mul.rn.f32x2 %0, %1, %2;" : "=l"(r.u) : "l"(a.u), "l"(b.u));
    return r;
}

// ---------------- gated delta-rule recurrence v2 ----------------
// 128 threads = 4 warps; each half-warp owns TWO adjacent DV-columns.
// State in registers; triple-buffered smem staging; one __syncthreads/step;
// all global loads prefetched one step ahead. grid (12, 32).
__global__ void __launch_bounds__(128, 3) delta_recur2(
    const float* __restrict__ Qn,  const float* __restrict__ Kn0, const float* __restrict__ Kn1,
    const float* __restrict__ Vs0, const float* __restrict__ Vs1,
    const float* __restrict__ Be0, const float* __restrict__ Be1,
    const float* __restrict__ Gd,  float* __restrict__ O)
{
    const int bh = blockIdx.x;
    const int b = bh / HH, h = bh % HH;
    const int tid = threadIdx.x;
    const int w = tid >> 5, lane = tid & 31;
    const int half = lane >> 4, l0 = lane & 15;
    const int col0 = blockIdx.y * 16 + w * 4 + half * 2;

    __shared__ __align__(16) float sk[3][3][256];   // [buf][k0,k1,q][dim]

    F2U S0[8], S1[8];
#pragma unroll
    for (int j = 0; j < 8; j++) { S0[j].u = 0ull; S1[j].u = 0ull; }

    {
        const size_t kb = (size_t)(b * TLEN) * KEY_DIM + h * DK + tid * 2;
        *reinterpret_cast<float2*>(&sk[0][0][tid * 2]) = *reinterpret_cast<const float2*>(Kn0 + kb);
        *reinterpret_cast<float2*>(&sk[0][1][tid * 2]) = *reinterpret_cast<const float2*>(Kn1 + kb);
        *reinterpret_cast<float2*>(&sk[0][2][tid * 2]) = *reinterpret_cast<const float2*>(Qn + kb);
    }
    const size_t vb0 = (size_t)(b * TLEN) * VAL_DIM + h * DV + col0;
    float2 vc0 = *reinterpret_cast<const float2*>(Vs0 + vb0);
    float2 vc1 = *reinterpret_cast<const float2*>(Vs1 + vb0);
    const int gi0 = (b * TLEN) * HH + h;
    float gcur = Gd[gi0], b0cur = Be0[gi0], b1cur = Be1[gi0];
    __syncthreads();

    int cur = 0;
    for (int t = 0; t < TLEN; t++) {
        const int nxt = (cur == 2) ? 0 : cur + 1;
        const int r = b * TLEN + t;
        const bool more = (t + 1 < TLEN);

        float2 kr0, kr1, krq, vn0, vn1;
        float gn = 0.f, bn0 = 0.f, bn1 = 0.f;
        if (more) {
            const size_t kb = (size_t)(r + 1) * KEY_DIM + h * DK + tid * 2;
            kr0 = *reinterpret_cast<const float2*>(Kn0 + kb);
            kr1 = *reinterpret_cast<const float2*>(Kn1 + kb);
            krq = *reinterpret_cast<const float2*>(Qn + kb);
            const size_t vb = (size_t)(r + 1) * VAL_DIM + h * DV + col0;
            vn0 = *reinterpret_cast<const float2*>(Vs0 + vb);
            vn1 = *reinterpret_cast<const float2*>(Vs1 + vb);
            const int gi = (r + 1) * HH + h;
            gn = Gd[gi]; bn0 = Be0[gi]; bn1 = Be1[gi];
        }

        const float decay = expf(gcur);
        const float2* pk0 = reinterpret_cast<const float2*>(sk[cur][0]);
        const float2* pk1 = reinterpret_cast<const float2*>(sk[cur][1]);
        const float2* pq  = reinterpret_cast<const float2*>(sk[cur][2]);

        F2U rk[8];
        // ---- pass 0: k0 ----
#pragma unroll
        for (int j = 0; j < 8; j++) rk[j].f = pk0[j * 16 + l0];
        F2U aA, aB; aA.u = 0ull; aB.u = 0ull;
#pragma unroll
        for (int j = 0; j < 8; j++) { aA = ffma2(rk[j], S0[j], aA); aB = ffma2(rk[j], S1[j], aB); }
        float dA = aA.f.x + aA.f.y, dB = aB.f.x + aB.f.y;
#pragma unroll
        for (int m = 8; m > 0; m >>= 1) {
            dA += __shfl_xor_sync(0xffffffffu, dA, m);
            dB += __shfl_xor_sync(0xffffffffu, dB, m);
        }
        dA *= decay; dB *= decay;
        const float u0A = (vc0.x - dA) * b0cur, u0B = (vc0.y - dB) * b0cur;
        F2U dec2; dec2.f = make_float2(decay, decay);
        F2U uA; uA.f = make_float2(u0A, u0A);
        F2U uB; uB.f = make_float2(u0B, u0B);
#pragma unroll
        for (int j = 0; j < 8; j++) {
            S0[j] = ffma2(S0[j], dec2, fmul2(rk[j], uA));
            S1[j] = ffma2(S1[j], dec2, fmul2(rk[j], uB));
        }
        // ---- pass 1: k1 ----
#pragma unroll
        for (int j = 0; j < 8; j++) rk[j].f = pk1[j * 16 + l0];
        aA.u = 0ull; aB.u = 0ull;
#pragma unroll
        for (int j = 0; j < 8; j++) { aA = ffma2(rk[j], S0[j], aA); aB = ffma2(rk[j], S1[j], aB); }
        dA = aA.f.x + aA.f.y; dB = aB.f.x + aB.f.y;
#pragma unroll
        for (int m = 8; m > 0; m >>= 1) {
            dA += __shfl_xor_sync(0xffffffffu, dA, m);
            dB += __shfl_xor_sync(0xffffffffu, dB, m);
        }
        const float u1A = (vc1.x - dA) * b1cur, u1B = (vc1.y - dB) * b1cur;
        uA.f = make_float2(u1A, u1A); uB.f = make_float2(u1B, u1B);
#pragma unroll
        for (int j = 0; j < 8; j++) {
            S0[j] = ffma2(rk[j], uA, S0[j]);
            S1[j] = ffma2(rk[j], uB, S1[j]);
        }
        // ---- readout: q ----
#pragma unroll
        for (int j = 0; j < 8; j++) rk[j].f = pq[j * 16 + l0];
        aA.u = 0ull; aB.u = 0ull;
#pragma unroll
        for (int j = 0; j < 8; j++) { aA = ffma2(rk[j], S0[j], aA); aB = ffma2(rk[j], S1[j], aB); }
        dA = aA.f.x + aA.f.y; dB = aB.f.x + aB.f.y;
#pragma unroll
        for (int m = 8; m > 0; m >>= 1) {
            dA += __shfl_xor_sync(0xffffffffu, dA, m);
            dB += __shfl_xor_sync(0xffffffffu, dB, m);
        }
        if (l0 == 0) {
            float2 ov; ov.x = dA; ov.y = dB;
            *reinterpret_cast<float2*>(O + (size_t)(r * HH + h) * DV + col0) = ov;
        }

        if (more) {
            *reinterpret_cast<float2*>(&sk[nxt][0][tid * 2]) = kr0;
            *reinterpret_cast<float2*>(&sk[nxt][1][tid * 2]) = kr1;
            *reinterpret_cast<float2*>(&sk[nxt][2][tid * 2]) = krq;
            vc0 = vn0; vc1 = vn1; gcur = gn; b0cur = bn0; b1cur = bn1;
            __syncthreads();
        }
        cur = nxt;
    }
}

// ---------------- RMS norm over DV + gated SiLU -> bf16 hi/lo ----------------
__global__ __launch_bounds__(256) void rms_gate(
    const float* __restrict__ Ob, const float* __restrict__ Gx,
    const float* __restrict__ onw,
    __nv_bfloat16* __restrict__ Yh, __nv_bfloat16* __restrict__ Yl)
{
    const int r = blockIdx.x, h = blockIdx.y, tid = threadIdx.x;
    const size_t base = (size_t)(r * HH + h) * DV;
    const size_t gbase = (size_t)r * PROJ_W + OFF_G + h * DV;
    float o0 = Ob[base + tid], o1 = Ob[base + tid + 256];
    __shared__ float sred[256];
    sred[tid] = o0 * o0 + o1 * o1;
    __syncthreads();
    for (int s = 128; s > 0; s >>= 1) {
        if (tid < s) sred[tid] += sred[tid + s];
        __syncthreads();
    }
    float scale = rsqrtf(sred[0] * (1.f / 512.f) + 1e-5f);
    float g0 = Gx[gbase + tid], g1 = Gx[gbase + tid + 256];
    float y0 = o0 * scale * onw[tid]       * (g0 / (1.f + expf(-g0)));
    float y1 = o1 * scale * onw[tid + 256] * (g1 / (1.f + expf(-g1)));
    __nv_bfloat16 h0 = __float2bfloat16_rn(y0);
    __nv_bfloat16 h1 = __float2bfloat16_rn(y1);
    Yh[base + tid]       = h0;
    Yh[base + tid + 256] = h1;
    Yl[base + tid]       = __float2bfloat16_rn(y0 - __bfloat162float(h0));
    Yl[base + tid + 256] = __float2bfloat16_rn(y1 - __bfloat162float(h1));
}

// ---------------- launch ----------------
extern "C" void kernel_launch(void* const* d_in, const int* in_sizes, int n_in,
                              void* d_out, int out_size)
{
    const float* x     = (const float*)d_in[0];
    const float* q_w   = (const float*)d_in[1];
    const float* k_ws  = (const float*)d_in[2];
    const float* v_ws  = (const float*)d_in[3];
    const float* b_ws  = (const float*)d_in[4];
    const float* a_w   = (const float*)d_in[5];
    const float* g_w   = (const float*)d_in[6];
    const float* o_w   = (const float*)d_in[7];
    const float* qcw   = (const float*)d_in[8];
    const float* kcw   = (const float*)d_in[9];
    const float* vcw   = (const float*)d_in[10];
    const float* A_log = (const float*)d_in[11];
    const float* dtb   = (const float*)d_in[12];
    const float* onw   = (const float*)d_in[13];
    float* out = (float*)d_out;

    float *proj, *qn, *kn0, *kn1, *vs0, *vs1, *ob;
    float *be0, *be1, *gd;
    __nv_bfloat16 *xhi, *xlo, *wch, *wcl, *owh, *owl, *ybh, *ybl;
    cudaGetSymbolAddress((void**)&proj, g_proj);
    cudaGetSymbolAddress((void**)&xhi, g_xhi);
    cudaGetSymbolAddress((void**)&xlo, g_xlo);
    cudaGetSymbolAddress((void**)&wch, g_wch);
    cudaGetSymbolAddress((void**)&wcl, g_wcl);
    cudaGetSymbolAddress((void**)&owh, g_owh);
    cudaGetSymbolAddress((void**)&owl, g_owl);
    cudaGetSymbolAddress((void**)&ybh, g_ybh);
    cudaGetSymbolAddress((void**)&ybl, g_ybl);
    cudaGetSymbolAddress((void**)&qn,  g_qn);
    cudaGetSymbolAddress((void**)&kn0, g_kn0);
    cudaGetSymbolAddress((void**)&kn1, g_kn1);
    cudaGetSymbolAddress((void**)&vs0, g_vs0);
    cudaGetSymbolAddress((void**)&vs1, g_vs1);
    cudaGetSymbolAddress((void**)&ob,  g_ob);
    cudaGetSymbolAddress((void**)&be0, g_be0);
    cudaGetSymbolAddress((void**)&be1, g_be1);
    cudaGetSymbolAddress((void**)&gd,  g_gd);

    cudaFuncSetAttribute(hgemm2, cudaFuncAttributeMaxDynamicSharedMemorySize, HSM3);

    // 1) input split
    {
        int n = RROWS * HID;
        cvt_split<<<(n/4 + 255)/256, 256>>>(x, xhi, xlo, n);
    }
    // 2) all weight splits (single launch)
    cvt_w_all<<<CVTW_BLOCKS, 256>>>(q_w, k_ws, v_ws, g_w, o_w, wch, wcl, owh, owl);

    // 3) merged projection GEMM
    hgemm2<<<dim3(PROJ_W/128, RROWS/128), 256, HSM3>>>(xhi, xlo, wch, wcl, proj, RROWS, PROJ_W, HID);

    // 4) fused tiny projections + activations
    gemm18<<<RROWS, 128>>>(x, b_ws, a_w, A_log, dtb, be0, be1, gd);

    // 5) all convs (single launch)
    conv_all<<<CONV_QK_BLOCKS + CONV_V_BLOCKS, 256>>>(proj, qcw, kcw, vcw, qn, kn0, kn1, vs0, vs1);

    // 6) sequential gated delta rule   (launch #6 -> ncu capture target)
    delta_recur2<<<dim3(BSZ * HH, DV / 16), 128>>>(qn, kn0, kn1, vs0, vs1, be0, be1, gd, ob);

    // 7) output norm + gate (emits bf16 hi/lo)
    rms_gate<<<dim3(RROWS, HH), 256>>>(ob, proj, onw, ybh, ybl);

    // 8) final projection
    hgemm2<<<dim3(HID/128, RROWS/128), 256, HSM3>>>(ybh, ybl, owh, owl, out, RROWS, HID, VAL_DIM);
}